// round 13
// baseline (speedup 1.0000x reference)
#include <cuda_runtime.h>
#include <cuda_bf16.h>
#include <cuda_fp16.h>
#include <cstdint>

#define BATCH   4
#define SEQ     2048
#define EMBED   1024
#define HEADS   16
#define HDIM    64
#define NGLOBAL 4
#define WINDOW  256

#define MROWS   (BATCH * SEQ)          // 8192
#define QKV_N   (3 * EMBED)            // 3072

// ---------------------------------------------------------------------------
// Scratch (device globals: allocation-guard-safe)
// ---------------------------------------------------------------------------
__device__ __half g_qkvh[(size_t)MROWS * QKV_N];   // fp16 hi (attn input)
__device__ __half g_qkvl[(size_t)MROWS * QKV_N];   // fp16 lo (Q cols only read)
__device__ __half g_xh  [(size_t)MROWS * EMBED];   // fp16 hi
__device__ __half g_xl  [(size_t)MROWS * EMBED];   // fp16 lo
__device__ __half g_wq16[(size_t)EMBED * QKV_N];   // fp16 weights
__device__ __half g_wo16[(size_t)EMBED * EMBED];
__device__ __half g_ctxh[(size_t)MROWS * EMBED];   // fp16 hi
__device__ __half g_ctxl[(size_t)MROWS * EMBED];   // fp16 lo

// ---------------------------------------------------------------------------
// Helpers
// ---------------------------------------------------------------------------
__device__ __forceinline__ void cp16(uint32_t dst, const void* src) {
    asm volatile("cp.async.cg.shared.global [%0], [%1], 16;\n"
                 :: "r"(dst), "l"(src));
}
__device__ __forceinline__ void ldsm4(uint32_t& r0, uint32_t& r1,
                                      uint32_t& r2, uint32_t& r3, uint32_t a) {
    asm volatile("ldmatrix.sync.aligned.m8n8.x4.shared.b16 {%0,%1,%2,%3},[%4];\n"
                 : "=r"(r0), "=r"(r1), "=r"(r2), "=r"(r3) : "r"(a));
}
__device__ __forceinline__ void ldsm4t(uint32_t& r0, uint32_t& r1,
                                       uint32_t& r2, uint32_t& r3, uint32_t a) {
    asm volatile("ldmatrix.sync.aligned.m8n8.x4.trans.shared.b16 {%0,%1,%2,%3},[%4];\n"
                 : "=r"(r0), "=r"(r1), "=r"(r2), "=r"(r3) : "r"(a));
}
// fp16 mma
__device__ __forceinline__ void mma16816h(float* c, const uint32_t* a,
                                          const uint32_t* b) {
    asm volatile(
        "mma.sync.aligned.m16n8k16.row.col.f32.f16.f16.f32 "
        "{%0,%1,%2,%3},{%4,%5,%6,%7},{%8,%9},{%0,%1,%2,%3};\n"
        : "+f"(c[0]), "+f"(c[1]), "+f"(c[2]), "+f"(c[3])
        : "r"(a[0]), "r"(a[1]), "r"(a[2]), "r"(a[3]), "r"(b[0]), "r"(b[1]));
}
// fp16 hi/lo packed split
__device__ __forceinline__ void split2h(float a, float b,
                                        uint32_t& h, uint32_t& l) {
    __half ha = __float2half_rn(a), hb = __float2half_rn(b);
    __half la = __float2half_rn(a - __half2float(ha));
    __half lb = __float2half_rn(b - __half2float(hb));
    h = ((uint32_t)__half_as_ushort(hb) << 16) | __half_as_ushort(ha);
    l = ((uint32_t)__half_as_ushort(lb) << 16) | __half_as_ushort(la);
}

// ---------------------------------------------------------------------------
// Prep kernels
// ---------------------------------------------------------------------------
__global__ void splith_kernel(const float* __restrict__ src,
                              __half* __restrict__ hi,
                              __half* __restrict__ lo, int n4)
{
    int i = blockIdx.x * blockDim.x + threadIdx.x;
    if (i >= n4) return;
    float4 v = ((const float4*)src)[i];
    uint32_t h0, l0, h1, l1;
    split2h(v.x, v.y, h0, l0);
    split2h(v.z, v.w, h1, l1);
    ((uint2*)hi)[i] = make_uint2(h0, h1);
    ((uint2*)lo)[i] = make_uint2(l0, l1);
}

__global__ void cvth_kernel(const float* __restrict__ src,
                            __half* __restrict__ dst, int n4)
{
    int i = blockIdx.x * blockDim.x + threadIdx.x;
    if (i >= n4) return;
    float4 v = ((const float4*)src)[i];
    __half2 a = __floats2half2_rn(v.x, v.y);
    __half2 b = __floats2half2_rn(v.z, v.w);
    ((uint2*)dst)[i] = make_uint2(*(uint32_t*)&a, *(uint32_t*)&b);
}

// ---------------------------------------------------------------------------
// fp16 tensor-core GEMM: C = (Ah[+Al]) @ B + bias, fp32 accum.
// Columns < n_two use the 2-term split; columns >= n_two use Ah only
// (1-term; skips Al loads + second mma). SPLIT: fp16 hi/lo C, else fp32 C.
// ---------------------------------------------------------------------------
#define BM 128
#define BN 128
#define BKK 64
#define ALD (BKK + 8)
#define BLD (BN + 8)
#define OFF_AH 0
#define OFF_AL (BM * ALD)
#define OFF_B  (2 * BM * ALD)
#define STAGE_H (2 * BM * ALD + BKK * BLD)
#define GEMM_SMEM (2 * STAGE_H * 2)

template <bool SPLIT>
__global__ __launch_bounds__(256, 2) void hsgemm(
    int M, int N, int K, int n_two,
    const __half* __restrict__ Ah, const __half* __restrict__ Al,
    const __half* __restrict__ B16,
    const float* __restrict__ bias, float* __restrict__ C,
    __half* __restrict__ Ch, __half* __restrict__ Cl)
{
    extern __shared__ __half sm[];
    const int tid = threadIdx.x;
    const int bm = blockIdx.y, bn = blockIdx.x;
    const int wid = tid >> 5, lane = tid & 31;
    const int wm = (wid >> 1) * 32, wn = (wid & 1) * 64;
    const bool two = (bn * BN) < n_two;        // uniform per-CTA

    const uint32_t smem_base = (uint32_t)__cvta_generic_to_shared(sm);

    float acc[2][8][4];
    #pragma unroll
    for (int mi = 0; mi < 2; mi++)
        #pragma unroll
        for (int nj = 0; nj < 8; nj++)
            #pragma unroll
            for (int r = 0; r < 4; r++) acc[mi][nj][r] = 0.f;

    const int NK = K / BKK;

    auto load_stage = [&](int s, int kt) {
        const uint32_t base = smem_base + s * (STAGE_H * 2);
        const int k0 = kt * BKK;
        #pragma unroll
        for (int i = 0; i < 4; i++) {
            int idx = tid + i * 256;
            int r = idx >> 3, c = (idx & 7) << 3;
            size_t aoff = (size_t)(bm * BM + r) * K + k0 + c;
            cp16(base + (OFF_AH + r * ALD + c) * 2, Ah + aoff);
            if (two) cp16(base + (OFF_AL + r * ALD + c) * 2, Al + aoff);
            int rb = idx >> 4, cb = (idx & 15) << 3;
            size_t boff = (size_t)(k0 + rb) * N + bn * BN + cb;
            cp16(base + (OFF_B + rb * BLD + cb) * 2, B16 + boff);
        }
        asm volatile("cp.async.commit_group;\n");
    };

    load_stage(0, 0);

    for (int kt = 0; kt < NK; kt++) {
        if (kt + 1 < NK) {
            load_stage((kt + 1) & 1, kt + 1);
            asm volatile("cp.async.wait_group 1;\n");
        } else {
            asm volatile("cp.async.wait_group 0;\n");
        }
        __syncthreads();

        const uint32_t base = smem_base + (kt & 1) * (STAGE_H * 2);

        #pragma unroll
        for (int ks = 0; ks < 4; ks++) {
            const int k = ks * 16;
            uint32_t ah[2][4], al[2][4];
            #pragma unroll
            for (int mi = 0; mi < 2; mi++) {
                int row = wm + mi * 16 + (lane & 15);
                int col = k + (lane >> 4) * 8;
                ldsm4(ah[mi][0], ah[mi][1], ah[mi][2], ah[mi][3],
                      base + (OFF_AH + row * ALD + col) * 2);
                if (two)
                    ldsm4(al[mi][0], al[mi][1], al[mi][2], al[mi][3],
                          base + (OFF_AL + row * ALD + col) * 2);
            }
            uint32_t bf[4][4];
            #pragma unroll
            for (int ng = 0; ng < 4; ng++) {
                int row = k + (lane & 15);
                int col = wn + ng * 16 + (lane >> 4) * 8;
                ldsm4t(bf[ng][0], bf[ng][1], bf[ng][2], bf[ng][3],
                       base + (OFF_B + row * BLD + col) * 2);
            }
            #pragma unroll
            for (int mi = 0; mi < 2; mi++) {
                #pragma unroll
                for (int nj = 0; nj < 8; nj++) {
                    const uint32_t* bp = &bf[nj >> 1][(nj & 1) * 2];
                    mma16816h(acc[mi][nj], ah[mi], bp);
                    if (two) mma16816h(acc[mi][nj], al[mi], bp);
                }
            }
        }
        __syncthreads();
    }

    #pragma unroll
    for (int mi = 0; mi < 2; mi++) {
        #pragma unroll
        for (int nj = 0; nj < 8; nj++) {
            int r0 = bm * BM + wm + mi * 16 + (lane >> 2);
            int c0 = bn * BN + wn + nj * 8 + (lane & 3) * 2;
            float b0 = bias[c0], b1 = bias[c0 + 1];
            float v00 = acc[mi][nj][0] + b0, v01 = acc[mi][nj][1] + b1;
            float v10 = acc[mi][nj][2] + b0, v11 = acc[mi][nj][3] + b1;
            if (SPLIT) {
                uint32_t hp, lp;
                split2h(v00, v01, hp, lp);
                *(uint32_t*)&Ch[(size_t)r0 * N + c0] = hp;
                *(uint32_t*)&Cl[(size_t)r0 * N + c0] = lp;
                split2h(v10, v11, hp, lp);
                *(uint32_t*)&Ch[(size_t)(r0 + 8) * N + c0] = hp;
                *(uint32_t*)&Cl[(size_t)(r0 + 8) * N + c0] = lp;
            } else {
                *(float2*)&C[(size_t)r0 * N + c0]       = make_float2(v00, v01);
                *(float2*)&C[(size_t)(r0 + 8) * N + c0] = make_float2(v10, v11);
            }
        }
    }
}

// ---------------------------------------------------------------------------
// Tensor-core flash attention (unchanged from R11): CTA = (64-query block,
// head, batch), 4 warps. fp16 2-term Q, 1-term K/V; ctx out fp16 hi/lo.
// ---------------------------------------------------------------------------
#define AP 72
#define ATT_SQH 0
#define ATT_SQL (64 * AP)
#define ATT_STAGE0 (2 * 64 * AP)
#define ATT_STAGE_SZ (2 * 64 * AP)        // K hi + V hi only
#define ATT_KH 0
#define ATT_VH (64 * AP)
#define ATT_SMEM ((2 * 64 * AP + 2 * 2 * 64 * AP) * 2)   // 55296 bytes

__global__ __launch_bounds__(128) void attn_tc(
    const __half* __restrict__ qh_g,
    const __half* __restrict__ ql_g,
    __half* __restrict__ ctxh,
    __half* __restrict__ ctxl)
{
    extern __shared__ __half smb[];
    const uint32_t sb = (uint32_t)__cvta_generic_to_shared(smb);
    const int qb = blockIdx.x, h = blockIdx.y, b = blockIdx.z;
    const int qs = qb * 64;
    const bool isg = (h < NGLOBAL);
    const int tid = threadIdx.x, lane = tid & 31, warp = tid >> 5;
    const int wq = warp * 16;
    const size_t rowbase = (size_t)(b * SEQ) * QKV_N;
    const float NEG_INF = __int_as_float(0xff800000u);

    #pragma unroll
    for (int i = 0; i < 4; i++) {
        int idx = tid + i * 128;
        int r = idx >> 3, c8 = (idx & 7) * 8;
        size_t src = rowbase + (size_t)(qs + r) * QKV_N + h * HDIM + c8;
        cp16(sb + (ATT_SQH + r * AP + c8) * 2, qh_g + src);
        cp16(sb + (ATT_SQL + r * AP + c8) * 2, ql_g + src);
    }
    asm volatile("cp.async.commit_group;\n");

    const int kb0 = isg ? 0 : max(0, qb - 4);

    auto load_kv = [&](int kb, int s) {
        const uint32_t base = sb + (ATT_STAGE0 + s * ATT_STAGE_SZ) * 2;
        const int ks = kb * 64;
        #pragma unroll
        for (int i = 0; i < 4; i++) {
            int idx = tid + i * 128;
            int r = idx >> 3, c8 = (idx & 7) * 8;
            size_t src = rowbase + (size_t)(ks + r) * QKV_N + EMBED + h * HDIM + c8;
            cp16(base + (ATT_KH + r * AP + c8) * 2, qh_g + src);
            cp16(base + (ATT_VH + r * AP + c8) * 2, qh_g + src + EMBED);
        }
        asm volatile("cp.async.commit_group;\n");
    };

    load_kv(kb0, 0);

    float m0 = -1e30f, m1 = -1e30f, l0 = 0.f, l1 = 0.f;
    float O[8][4];
    #pragma unroll
    for (int nj = 0; nj < 8; nj++)
        #pragma unroll
        for (int r = 0; r < 4; r++) O[nj][r] = 0.f;

    uint32_t qfh[4][4], qfl[4][4];
    bool qloaded = false;

    for (int kb = kb0; kb <= qb; kb++) {
        const int s = (kb - kb0) & 1;
        const int ks = kb * 64;
        __syncthreads();
        if (kb < qb) {
            load_kv(kb + 1, s ^ 1);
            asm volatile("cp.async.wait_group 1;\n");
        } else {
            asm volatile("cp.async.wait_group 0;\n");
        }
        __syncthreads();

        if (!qloaded) {
            qloaded = true;
            #pragma unroll
            for (int kt = 0; kt < 4; kt++) {
                uint32_t a = sb + (ATT_SQH + (wq + (lane & 15)) * AP
                                   + kt * 16 + 8 * (lane >> 4)) * 2;
                ldsm4(qfh[kt][0], qfh[kt][1], qfh[kt][2], qfh[kt][3], a);
                ldsm4(qfl[kt][0], qfl[kt][1], qfl[kt][2], qfl[kt][3],
                      a + (ATT_SQL - ATT_SQH) * 2);
            }
        }

        const uint32_t kbase = sb + (ATT_STAGE0 + s * ATT_STAGE_SZ) * 2;

        float sf[8][4];
        #pragma unroll
        for (int nj = 0; nj < 8; nj++)
            #pragma unroll
            for (int r = 0; r < 4; r++) sf[nj][r] = 0.f;

        #pragma unroll
        for (int kt = 0; kt < 4; kt++) {
            #pragma unroll
            for (int ng = 0; ng < 4; ng++) {
                uint32_t kh[4];
                uint32_t a = kbase + ((ng * 16 + (lane & 15)) * AP
                                      + kt * 16 + 8 * (lane >> 4)) * 2;
                ldsm4(kh[0], kh[1], kh[2], kh[3], a + ATT_KH * 2);
                uint32_t bh0[2] = {kh[0], kh[2]}, bh1[2] = {kh[1], kh[3]};
                mma16816h(sf[2 * ng],     qfh[kt], bh0);
                mma16816h(sf[2 * ng],     qfl[kt], bh0);
                mma16816h(sf[2 * ng + 1], qfh[kt], bh1);
                mma16816h(sf[2 * ng + 1], qfl[kt], bh1);
            }
        }
        #pragma unroll
        for (int nj = 0; nj < 8; nj++)
            #pragma unroll
            for (int r = 0; r < 4; r++) sf[nj][r] *= 0.125f;

        const int i0 = qs + wq + (lane >> 2);
        const int i1 = i0 + 8;
        const int mode = (kb == qb) ? 1 : ((!isg && (qb - kb) == 4) ? 2 : 0);
        if (mode == 1) {
            #pragma unroll
            for (int nj = 0; nj < 8; nj++) {
                int j0 = ks + nj * 8 + (lane & 3) * 2, j1 = j0 + 1;
                if (j0 > i0) sf[nj][0] = NEG_INF;
                if (j1 > i0) sf[nj][1] = NEG_INF;
                if (j0 > i1) sf[nj][2] = NEG_INF;
                if (j1 > i1) sf[nj][3] = NEG_INF;
            }
        } else if (mode == 2) {
            #pragma unroll
            for (int nj = 0; nj < 8; nj++) {
                int j0 = ks + nj * 8 + (lane & 3) * 2, j1 = j0 + 1;
                if (i0 - j0 > WINDOW) sf[nj][0] = NEG_INF;
                if (i0 - j1 > WINDOW) sf[nj][1] = NEG_INF;
                if (i1 - j0 > WINDOW) sf[nj][2] = NEG_INF;
                if (i1 - j1 > WINDOW) sf[nj][3] = NEG_INF;
            }
        }

        float mx0 = -1e30f, mx1 = -1e30f;
        #pragma unroll
        for (int nj = 0; nj < 8; nj++) {
            mx0 = fmaxf(mx0, fmaxf(sf[nj][0], sf[nj][1]));
            mx1 = fmaxf(mx1, fmaxf(sf[nj][2], sf[nj][3]));
        }
        mx0 = fmaxf(mx0, __shfl_xor_sync(0xffffffffu, mx0, 1));
        mx0 = fmaxf(mx0, __shfl_xor_sync(0xffffffffu, mx0, 2));
        mx1 = fmaxf(mx1, __shfl_xor_sync(0xffffffffu, mx1, 1));
        mx1 = fmaxf(mx1, __shfl_xor_sync(0xffffffffu, mx1, 2));
        const float mn0 = fmaxf(m0, mx0), mn1 = fmaxf(m1, mx1);
        float s0 = 0.f, s1 = 0.f;
        #pragma unroll
        for (int nj = 0; nj < 8; nj++) {
            sf[nj][0] = __expf(sf[nj][0] - mn0);
            sf[nj][1] = __expf(sf[nj][1] - mn0);
            sf[nj][2] = __expf(sf[nj][2] - mn1);
            sf[nj][3] = __expf(sf[nj][3] - mn1);
            s0 += sf[nj][0] + sf[nj][1];
            s1 += sf[nj][2] + sf[nj][3];
        }
        s0 += __shfl_xor_sync(0xffffffffu, s0, 1);
        s0 += __shfl_xor_sync(0xffffffffu, s0, 2);
        s1 += __shfl_xor_sync(0xffffffffu, s1, 1);
        s1 += __shfl_xor_sync(0xffffffffu, s1, 2);
        const float a0 = __expf(m0 - mn0), a1 = __expf(m1 - mn1);
        l0 = l0 * a0 + s0; l1 = l1 * a1 + s1;
        m0 = mn0; m1 = mn1;
        #pragma unroll
        for (int nj = 0; nj < 8; nj++) {
            O[nj][0] *= a0; O[nj][1] *= a0;
            O[nj][2] *= a1; O[nj][3] *= a1;
        }

        #pragma unroll
        for (int kt = 0; kt < 4; kt++) {
            uint32_t pah[4], pal[4];
            split2h(sf[2 * kt][0],     sf[2 * kt][1],     pah[0], pal[0]);
            split2h(sf[2 * kt][2],     sf[2 * kt][3],     pah[1], pal[1]);
            split2h(sf[2 * kt + 1][0], sf[2 * kt + 1][1], pah[2], pal[2]);
            split2h(sf[2 * kt + 1][2], sf[2 * kt + 1][3], pah[3], pal[3]);
            #pragma unroll
            for (int ng = 0; ng < 4; ng++) {
                uint32_t vh[4];
                uint32_t a = kbase + ((kt * 16 + (lane & 15)) * AP
                                      + ng * 16 + 8 * (lane >> 4)) * 2;
                ldsm4t(vh[0], vh[1], vh[2], vh[3], a + ATT_VH * 2);
                mma16816h(O[2 * ng],     pah, &vh[0]);
                mma16816h(O[2 * ng],     pal, &vh[0]);
                mma16816h(O[2 * ng + 1], pah, &vh[2]);
                mma16816h(O[2 * ng + 1], pal, &vh[2]);
            }
        }
    }

    const float inv0 = 1.f / l0, inv1 = 1.f / l1;
    const int r0g = qs + wq + (lane >> 2);
    const size_t base0 = ((size_t)(b * SEQ + r0g)) * EMBED + h * HDIM;
    #pragma unroll
    for (int nj = 0; nj < 8; nj++) {
        const int c = nj * 8 + (lane & 3) * 2;
        uint32_t hp, lp;
        split2h(O[nj][0] * inv0, O[nj][1] * inv0, hp, lp);
        *(uint32_t*)&ctxh[base0 + c] = hp;
        *(uint32_t*)&ctxl[base0 + c] = lp;
        split2h(O[nj][2] * inv1, O[nj][3] * inv1, hp, lp);
        *(uint32_t*)&ctxh[base0 + (size_t)8 * EMBED + c] = hp;
        *(uint32_t*)&ctxl[base0 + (size_t)8 * EMBED + c] = lp;
    }
}

// ---------------------------------------------------------------------------
// Launch
// ---------------------------------------------------------------------------
extern "C" void kernel_launch(void* const* d_in, const int* in_sizes, int n_in,
                              void* d_out, int out_size)
{
    const float* x     = (const float*)d_in[0];
    const float* w_qkv = (const float*)d_in[1];
    const float* b_qkv = (const float*)d_in[2];
    const float* w_out = (const float*)d_in[3];
    const float* b_out = (const float*)d_in[4];
    float* out = (float*)d_out;

    __half *qkvh, *qkvl, *xh, *xl, *wq16, *wo16, *ctxh, *ctxl;
    cudaGetSymbolAddress((void**)&qkvh, g_qkvh);
    cudaGetSymbolAddress((void**)&qkvl, g_qkvl);
    cudaGetSymbolAddress((void**)&xh,   g_xh);
    cudaGetSymbolAddress((void**)&xl,   g_xl);
    cudaGetSymbolAddress((void**)&wq16, g_wq16);
    cudaGetSymbolAddress((void**)&wo16, g_wo16);
    cudaGetSymbolAddress((void**)&ctxh, g_ctxh);
    cudaGetSymbolAddress((void**)&ctxl, g_ctxl);

    cudaFuncSetAttribute(hsgemm<true>,  cudaFuncAttributeMaxDynamicSharedMemorySize, GEMM_SMEM);
    cudaFuncSetAttribute(hsgemm<false>, cudaFuncAttributeMaxDynamicSharedMemorySize, GEMM_SMEM);
    cudaFuncSetAttribute(attn_tc, cudaFuncAttributeMaxDynamicSharedMemorySize, ATT_SMEM);

    // 0) x -> fp16 hi/lo; weights -> fp16
    {
        int n4 = MROWS * EMBED / 4;
        splith_kernel<<<(n4 + 255) / 256, 256>>>(x, xh, xl, n4);
        n4 = EMBED * QKV_N / 4;
        cvth_kernel<<<(n4 + 255) / 256, 256>>>(w_qkv, wq16, n4);
        n4 = EMBED * EMBED / 4;
        cvth_kernel<<<(n4 + 255) / 256, 256>>>(w_out, wo16, n4);
    }

    // 1) QKV projection: Q columns (<1024) 2-term, K/V columns 1-term
    {
        dim3 grid(QKV_N / BN, MROWS / BM);
        hsgemm<true><<<grid, 256, GEMM_SMEM>>>(MROWS, QKV_N, EMBED, EMBED,
                                               xh, xl, wq16, b_qkv,
                                               nullptr, qkvh, qkvl);
    }
    // 2) Tensor-core attention -> fp16 hi/lo ctx
    {
        dim3 grid(SEQ / 64, HEADS, BATCH);
        attn_tc<<<grid, 128, ATT_SMEM>>>(qkvh, qkvl, ctxh, ctxl);
    }
    // 3) Output projection: full 2-term (output-critical)
    {
        dim3 grid(EMBED / BN, MROWS / BM);
        hsgemm<false><<<grid, 256, GEMM_SMEM>>>(MROWS, EMBED, EMBED, EMBED,
                                                ctxh, ctxl, wo16, b_out,
                                                out, nullptr, nullptr);
    }
}

// round 14
// speedup vs baseline: 1.1233x; 1.1233x over previous
#include <cuda_runtime.h>
#include <cuda_bf16.h>
#include <cuda_fp16.h>
#include <cstdint>

#define BATCH   4
#define SEQ     2048
#define EMBED   1024
#define HEADS   16
#define HDIM    64
#define NGLOBAL 4
#define WINDOW  256

#define MROWS   (BATCH * SEQ)          // 8192
#define QKV_N   (3 * EMBED)            // 3072

// ---------------------------------------------------------------------------
// Scratch (device globals: allocation-guard-safe)
// ---------------------------------------------------------------------------
__device__ __half g_qkvh[(size_t)MROWS * QKV_N];   // fp16 hi (attn input)
__device__ __half g_qkvl[(size_t)MROWS * QKV_N];   // fp16 lo (Q cols only read)
__device__ __half g_xh  [(size_t)MROWS * EMBED];   // fp16 hi
__device__ __half g_xl  [(size_t)MROWS * EMBED];   // fp16 lo
__device__ __half g_wq16[(size_t)EMBED * QKV_N];   // fp16 weights
__device__ __half g_wo16[(size_t)EMBED * EMBED];
__device__ __half g_ctxh[(size_t)MROWS * EMBED];   // fp16 hi
__device__ __half g_ctxl[(size_t)MROWS * EMBED];   // fp16 lo

// ---------------------------------------------------------------------------
// Helpers
// ---------------------------------------------------------------------------
__device__ __forceinline__ void cp16(uint32_t dst, const void* src) {
    asm volatile("cp.async.cg.shared.global [%0], [%1], 16;\n"
                 :: "r"(dst), "l"(src));
}
__device__ __forceinline__ void ldsm4(uint32_t& r0, uint32_t& r1,
                                      uint32_t& r2, uint32_t& r3, uint32_t a) {
    asm volatile("ldmatrix.sync.aligned.m8n8.x4.shared.b16 {%0,%1,%2,%3},[%4];\n"
                 : "=r"(r0), "=r"(r1), "=r"(r2), "=r"(r3) : "r"(a));
}
__device__ __forceinline__ void ldsm4t(uint32_t& r0, uint32_t& r1,
                                       uint32_t& r2, uint32_t& r3, uint32_t a) {
    asm volatile("ldmatrix.sync.aligned.m8n8.x4.trans.shared.b16 {%0,%1,%2,%3},[%4];\n"
                 : "=r"(r0), "=r"(r1), "=r"(r2), "=r"(r3) : "r"(a));
}
// fp16 mma
__device__ __forceinline__ void mma16816h(float* c, const uint32_t* a,
                                          const uint32_t* b) {
    asm volatile(
        "mma.sync.aligned.m16n8k16.row.col.f32.f16.f16.f32 "
        "{%0,%1,%2,%3},{%4,%5,%6,%7},{%8,%9},{%0,%1,%2,%3};\n"
        : "+f"(c[0]), "+f"(c[1]), "+f"(c[2]), "+f"(c[3])
        : "r"(a[0]), "r"(a[1]), "r"(a[2]), "r"(a[3]), "r"(b[0]), "r"(b[1]));
}
// fp16 hi/lo packed split
__device__ __forceinline__ void split2h(float a, float b,
                                        uint32_t& h, uint32_t& l) {
    __half ha = __float2half_rn(a), hb = __float2half_rn(b);
    __half la = __float2half_rn(a - __half2float(ha));
    __half lb = __float2half_rn(b - __half2float(hb));
    h = ((uint32_t)__half_as_ushort(hb) << 16) | __half_as_ushort(ha);
    l = ((uint32_t)__half_as_ushort(lb) << 16) | __half_as_ushort(la);
}

// ---------------------------------------------------------------------------
// Prep kernels
// ---------------------------------------------------------------------------
__global__ void splith_kernel(const float* __restrict__ src,
                              __half* __restrict__ hi,
                              __half* __restrict__ lo, int n4)
{
    int i = blockIdx.x * blockDim.x + threadIdx.x;
    if (i >= n4) return;
    float4 v = ((const float4*)src)[i];
    uint32_t h0, l0, h1, l1;
    split2h(v.x, v.y, h0, l0);
    split2h(v.z, v.w, h1, l1);
    ((uint2*)hi)[i] = make_uint2(h0, h1);
    ((uint2*)lo)[i] = make_uint2(l0, l1);
}

__global__ void cvth_kernel(const float* __restrict__ src,
                            __half* __restrict__ dst, int n4)
{
    int i = blockIdx.x * blockDim.x + threadIdx.x;
    if (i >= n4) return;
    float4 v = ((const float4*)src)[i];
    __half2 a = __floats2half2_rn(v.x, v.y);
    __half2 b = __floats2half2_rn(v.z, v.w);
    ((uint2*)dst)[i] = make_uint2(*(uint32_t*)&a, *(uint32_t*)&b);
}

// ---------------------------------------------------------------------------
// fp16 tensor-core GEMM: C[:, n0 + bn*BN ...] = (Ah[+Al]) @ B + bias.
// TERMS is a COMPILE-TIME parameter (1 or 2) so the 1-term path has the
// Al loads/ldsm/mma dead-code-eliminated (no predicated HMMA).
// SPLIT: fp16 hi/lo C, else fp32 C. n0 = column offset of this launch.
// ---------------------------------------------------------------------------
#define BM 128
#define BN 128
#define BKK 64
#define ALD (BKK + 8)
#define BLD (BN + 8)
#define OFF_AH 0
#define OFF_AL (BM * ALD)
#define OFF_B  (2 * BM * ALD)
#define STAGE_H (2 * BM * ALD + BKK * BLD)
#define GEMM_SMEM (2 * STAGE_H * 2)

template <bool SPLIT, int TERMS>
__global__ __launch_bounds__(256, 2) void hsgemm(
    int M, int N, int K, int n0,
    const __half* __restrict__ Ah, const __half* __restrict__ Al,
    const __half* __restrict__ B16,
    const float* __restrict__ bias, float* __restrict__ C,
    __half* __restrict__ Ch, __half* __restrict__ Cl)
{
    extern __shared__ __half sm[];
    const int tid = threadIdx.x;
    const int bm = blockIdx.y;
    const int cb = n0 + blockIdx.x * BN;       // global column base
    const int wid = tid >> 5, lane = tid & 31;
    const int wm = (wid >> 1) * 32, wn = (wid & 1) * 64;

    const uint32_t smem_base = (uint32_t)__cvta_generic_to_shared(sm);

    float acc[2][8][4];
    #pragma unroll
    for (int mi = 0; mi < 2; mi++)
        #pragma unroll
        for (int nj = 0; nj < 8; nj++)
            #pragma unroll
            for (int r = 0; r < 4; r++) acc[mi][nj][r] = 0.f;

    const int NK = K / BKK;

    auto load_stage = [&](int s, int kt) {
        const uint32_t base = smem_base + s * (STAGE_H * 2);
        const int k0 = kt * BKK;
        #pragma unroll
        for (int i = 0; i < 4; i++) {
            int idx = tid + i * 256;
            int r = idx >> 3, c = (idx & 7) << 3;
            size_t aoff = (size_t)(bm * BM + r) * K + k0 + c;
            cp16(base + (OFF_AH + r * ALD + c) * 2, Ah + aoff);
            if (TERMS == 2)
                cp16(base + (OFF_AL + r * ALD + c) * 2, Al + aoff);
            int rb = idx >> 4, cbk = (idx & 15) << 3;
            size_t boff = (size_t)(k0 + rb) * N + cb + cbk;
            cp16(base + (OFF_B + rb * BLD + cbk) * 2, B16 + boff);
        }
        asm volatile("cp.async.commit_group;\n");
    };

    load_stage(0, 0);

    for (int kt = 0; kt < NK; kt++) {
        if (kt + 1 < NK) {
            load_stage((kt + 1) & 1, kt + 1);
            asm volatile("cp.async.wait_group 1;\n");
        } else {
            asm volatile("cp.async.wait_group 0;\n");
        }
        __syncthreads();

        const uint32_t base = smem_base + (kt & 1) * (STAGE_H * 2);

        #pragma unroll
        for (int ks = 0; ks < 4; ks++) {
            const int k = ks * 16;
            uint32_t ah[2][4], al[2][4];
            #pragma unroll
            for (int mi = 0; mi < 2; mi++) {
                int row = wm + mi * 16 + (lane & 15);
                int col = k + (lane >> 4) * 8;
                ldsm4(ah[mi][0], ah[mi][1], ah[mi][2], ah[mi][3],
                      base + (OFF_AH + row * ALD + col) * 2);
                if (TERMS == 2)
                    ldsm4(al[mi][0], al[mi][1], al[mi][2], al[mi][3],
                          base + (OFF_AL + row * ALD + col) * 2);
            }
            uint32_t bf[4][4];
            #pragma unroll
            for (int ng = 0; ng < 4; ng++) {
                int row = k + (lane & 15);
                int col = wn + ng * 16 + (lane >> 4) * 8;
                ldsm4t(bf[ng][0], bf[ng][1], bf[ng][2], bf[ng][3],
                       base + (OFF_B + row * BLD + col) * 2);
            }
            #pragma unroll
            for (int mi = 0; mi < 2; mi++) {
                #pragma unroll
                for (int nj = 0; nj < 8; nj++) {
                    const uint32_t* bp = &bf[nj >> 1][(nj & 1) * 2];
                    mma16816h(acc[mi][nj], ah[mi], bp);
                    if (TERMS == 2) mma16816h(acc[mi][nj], al[mi], bp);
                }
            }
        }
        __syncthreads();
    }

    #pragma unroll
    for (int mi = 0; mi < 2; mi++) {
        #pragma unroll
        for (int nj = 0; nj < 8; nj++) {
            int r0 = bm * BM + wm + mi * 16 + (lane >> 2);
            int c0 = cb + wn + nj * 8 + (lane & 3) * 2;
            float b0 = bias[c0], b1 = bias[c0 + 1];
            float v00 = acc[mi][nj][0] + b0, v01 = acc[mi][nj][1] + b1;
            float v10 = acc[mi][nj][2] + b0, v11 = acc[mi][nj][3] + b1;
            if (SPLIT) {
                uint32_t hp, lp;
                split2h(v00, v01, hp, lp);
                *(uint32_t*)&Ch[(size_t)r0 * N + c0] = hp;
                *(uint32_t*)&Cl[(size_t)r0 * N + c0] = lp;
                split2h(v10, v11, hp, lp);
                *(uint32_t*)&Ch[(size_t)(r0 + 8) * N + c0] = hp;
                *(uint32_t*)&Cl[(size_t)(r0 + 8) * N + c0] = lp;
            } else {
                *(float2*)&C[(size_t)r0 * N + c0]       = make_float2(v00, v01);
                *(float2*)&C[(size_t)(r0 + 8) * N + c0] = make_float2(v10, v11);
            }
        }
    }
}

// ---------------------------------------------------------------------------
// Tensor-core flash attention (unchanged from R11/R13): CTA = (64-query
// block, head, batch), 4 warps. fp16 2-term Q, 1-term K/V; ctx out hi/lo.
// ---------------------------------------------------------------------------
#define AP 72
#define ATT_SQH 0
#define ATT_SQL (64 * AP)
#define ATT_STAGE0 (2 * 64 * AP)
#define ATT_STAGE_SZ (2 * 64 * AP)        // K hi + V hi only
#define ATT_KH 0
#define ATT_VH (64 * AP)
#define ATT_SMEM ((2 * 64 * AP + 2 * 2 * 64 * AP) * 2)   // 55296 bytes

__global__ __launch_bounds__(128) void attn_tc(
    const __half* __restrict__ qh_g,
    const __half* __restrict__ ql_g,
    __half* __restrict__ ctxh,
    __half* __restrict__ ctxl)
{
    extern __shared__ __half smb[];
    const uint32_t sb = (uint32_t)__cvta_generic_to_shared(smb);
    const int qb = blockIdx.x, h = blockIdx.y, b = blockIdx.z;
    const int qs = qb * 64;
    const bool isg = (h < NGLOBAL);
    const int tid = threadIdx.x, lane = tid & 31, warp = tid >> 5;
    const int wq = warp * 16;
    const size_t rowbase = (size_t)(b * SEQ) * QKV_N;
    const float NEG_INF = __int_as_float(0xff800000u);

    #pragma unroll
    for (int i = 0; i < 4; i++) {
        int idx = tid + i * 128;
        int r = idx >> 3, c8 = (idx & 7) * 8;
        size_t src = rowbase + (size_t)(qs + r) * QKV_N + h * HDIM + c8;
        cp16(sb + (ATT_SQH + r * AP + c8) * 2, qh_g + src);
        cp16(sb + (ATT_SQL + r * AP + c8) * 2, ql_g + src);
    }
    asm volatile("cp.async.commit_group;\n");

    const int kb0 = isg ? 0 : max(0, qb - 4);

    auto load_kv = [&](int kb, int s) {
        const uint32_t base = sb + (ATT_STAGE0 + s * ATT_STAGE_SZ) * 2;
        const int ks = kb * 64;
        #pragma unroll
        for (int i = 0; i < 4; i++) {
            int idx = tid + i * 128;
            int r = idx >> 3, c8 = (idx & 7) * 8;
            size_t src = rowbase + (size_t)(ks + r) * QKV_N + EMBED + h * HDIM + c8;
            cp16(base + (ATT_KH + r * AP + c8) * 2, qh_g + src);
            cp16(base + (ATT_VH + r * AP + c8) * 2, qh_g + src + EMBED);
        }
        asm volatile("cp.async.commit_group;\n");
    };

    load_kv(kb0, 0);

    float m0 = -1e30f, m1 = -1e30f, l0 = 0.f, l1 = 0.f;
    float O[8][4];
    #pragma unroll
    for (int nj = 0; nj < 8; nj++)
        #pragma unroll
        for (int r = 0; r < 4; r++) O[nj][r] = 0.f;

    uint32_t qfh[4][4], qfl[4][4];
    bool qloaded = false;

    for (int kb = kb0; kb <= qb; kb++) {
        const int s = (kb - kb0) & 1;
        const int ks = kb * 64;
        __syncthreads();
        if (kb < qb) {
            load_kv(kb + 1, s ^ 1);
            asm volatile("cp.async.wait_group 1;\n");
        } else {
            asm volatile("cp.async.wait_group 0;\n");
        }
        __syncthreads();

        if (!qloaded) {
            qloaded = true;
            #pragma unroll
            for (int kt = 0; kt < 4; kt++) {
                uint32_t a = sb + (ATT_SQH + (wq + (lane & 15)) * AP
                                   + kt * 16 + 8 * (lane >> 4)) * 2;
                ldsm4(qfh[kt][0], qfh[kt][1], qfh[kt][2], qfh[kt][3], a);
                ldsm4(qfl[kt][0], qfl[kt][1], qfl[kt][2], qfl[kt][3],
                      a + (ATT_SQL - ATT_SQH) * 2);
            }
        }

        const uint32_t kbase = sb + (ATT_STAGE0 + s * ATT_STAGE_SZ) * 2;

        float sf[8][4];
        #pragma unroll
        for (int nj = 0; nj < 8; nj++)
            #pragma unroll
            for (int r = 0; r < 4; r++) sf[nj][r] = 0.f;

        #pragma unroll
        for (int kt = 0; kt < 4; kt++) {
            #pragma unroll
            for (int ng = 0; ng < 4; ng++) {
                uint32_t kh[4];
                uint32_t a = kbase + ((ng * 16 + (lane & 15)) * AP
                                      + kt * 16 + 8 * (lane >> 4)) * 2;
                ldsm4(kh[0], kh[1], kh[2], kh[3], a + ATT_KH * 2);
                uint32_t bh0[2] = {kh[0], kh[2]}, bh1[2] = {kh[1], kh[3]};
                mma16816h(sf[2 * ng],     qfh[kt], bh0);
                mma16816h(sf[2 * ng],     qfl[kt], bh0);
                mma16816h(sf[2 * ng + 1], qfh[kt], bh1);
                mma16816h(sf[2 * ng + 1], qfl[kt], bh1);
            }
        }
        #pragma unroll
        for (int nj = 0; nj < 8; nj++)
            #pragma unroll
            for (int r = 0; r < 4; r++) sf[nj][r] *= 0.125f;

        const int i0 = qs + wq + (lane >> 2);
        const int i1 = i0 + 8;
        const int mode = (kb == qb) ? 1 : ((!isg && (qb - kb) == 4) ? 2 : 0);
        if (mode == 1) {
            #pragma unroll
            for (int nj = 0; nj < 8; nj++) {
                int j0 = ks + nj * 8 + (lane & 3) * 2, j1 = j0 + 1;
                if (j0 > i0) sf[nj][0] = NEG_INF;
                if (j1 > i0) sf[nj][1] = NEG_INF;
                if (j0 > i1) sf[nj][2] = NEG_INF;
                if (j1 > i1) sf[nj][3] = NEG_INF;
            }
        } else if (mode == 2) {
            #pragma unroll
            for (int nj = 0; nj < 8; nj++) {
                int j0 = ks + nj * 8 + (lane & 3) * 2, j1 = j0 + 1;
                if (i0 - j0 > WINDOW) sf[nj][0] = NEG_INF;
                if (i0 - j1 > WINDOW) sf[nj][1] = NEG_INF;
                if (i1 - j0 > WINDOW) sf[nj][2] = NEG_INF;
                if (i1 - j1 > WINDOW) sf[nj][3] = NEG_INF;
            }
        }

        float mx0 = -1e30f, mx1 = -1e30f;
        #pragma unroll
        for (int nj = 0; nj < 8; nj++) {
            mx0 = fmaxf(mx0, fmaxf(sf[nj][0], sf[nj][1]));
            mx1 = fmaxf(mx1, fmaxf(sf[nj][2], sf[nj][3]));
        }
        mx0 = fmaxf(mx0, __shfl_xor_sync(0xffffffffu, mx0, 1));
        mx0 = fmaxf(mx0, __shfl_xor_sync(0xffffffffu, mx0, 2));
        mx1 = fmaxf(mx1, __shfl_xor_sync(0xffffffffu, mx1, 1));
        mx1 = fmaxf(mx1, __shfl_xor_sync(0xffffffffu, mx1, 2));
        const float mn0 = fmaxf(m0, mx0), mn1 = fmaxf(m1, mx1);
        float s0 = 0.f, s1 = 0.f;
        #pragma unroll
        for (int nj = 0; nj < 8; nj++) {
            sf[nj][0] = __expf(sf[nj][0] - mn0);
            sf[nj][1] = __expf(sf[nj][1] - mn0);
            sf[nj][2] = __expf(sf[nj][2] - mn1);
            sf[nj][3] = __expf(sf[nj][3] - mn1);
            s0 += sf[nj][0] + sf[nj][1];
            s1 += sf[nj][2] + sf[nj][3];
        }
        s0 += __shfl_xor_sync(0xffffffffu, s0, 1);
        s0 += __shfl_xor_sync(0xffffffffu, s0, 2);
        s1 += __shfl_xor_sync(0xffffffffu, s1, 1);
        s1 += __shfl_xor_sync(0xffffffffu, s1, 2);
        const float a0 = __expf(m0 - mn0), a1 = __expf(m1 - mn1);
        l0 = l0 * a0 + s0; l1 = l1 * a1 + s1;
        m0 = mn0; m1 = mn1;
        #pragma unroll
        for (int nj = 0; nj < 8; nj++) {
            O[nj][0] *= a0; O[nj][1] *= a0;
            O[nj][2] *= a1; O[nj][3] *= a1;
        }

        #pragma unroll
        for (int kt = 0; kt < 4; kt++) {
            uint32_t pah[4], pal[4];
            split2h(sf[2 * kt][0],     sf[2 * kt][1],     pah[0], pal[0]);
            split2h(sf[2 * kt][2],     sf[2 * kt][3],     pah[1], pal[1]);
            split2h(sf[2 * kt + 1][0], sf[2 * kt + 1][1], pah[2], pal[2]);
            split2h(sf[2 * kt + 1][2], sf[2 * kt + 1][3], pah[3], pal[3]);
            #pragma unroll
            for (int ng = 0; ng < 4; ng++) {
                uint32_t vh[4];
                uint32_t a = kbase + ((kt * 16 + (lane & 15)) * AP
                                      + ng * 16 + 8 * (lane >> 4)) * 2;
                ldsm4t(vh[0], vh[1], vh[2], vh[3], a + ATT_VH * 2);
                mma16816h(O[2 * ng],     pah, &vh[0]);
                mma16816h(O[2 * ng],     pal, &vh[0]);
                mma16816h(O[2 * ng + 1], pah, &vh[2]);
                mma16816h(O[2 * ng + 1], pal, &vh[2]);
            }
        }
    }

    const float inv0 = 1.f / l0, inv1 = 1.f / l1;
    const int r0g = qs + wq + (lane >> 2);
    const size_t base0 = ((size_t)(b * SEQ + r0g)) * EMBED + h * HDIM;
    #pragma unroll
    for (int nj = 0; nj < 8; nj++) {
        const int c = nj * 8 + (lane & 3) * 2;
        uint32_t hp, lp;
        split2h(O[nj][0] * inv0, O[nj][1] * inv0, hp, lp);
        *(uint32_t*)&ctxh[base0 + c] = hp;
        *(uint32_t*)&ctxl[base0 + c] = lp;
        split2h(O[nj][2] * inv1, O[nj][3] * inv1, hp, lp);
        *(uint32_t*)&ctxh[base0 + (size_t)8 * EMBED + c] = hp;
        *(uint32_t*)&ctxl[base0 + (size_t)8 * EMBED + c] = lp;
    }
}

// ---------------------------------------------------------------------------
// Launch
// ---------------------------------------------------------------------------
extern "C" void kernel_launch(void* const* d_in, const int* in_sizes, int n_in,
                              void* d_out, int out_size)
{
    const float* x     = (const float*)d_in[0];
    const float* w_qkv = (const float*)d_in[1];
    const float* b_qkv = (const float*)d_in[2];
    const float* w_out = (const float*)d_in[3];
    const float* b_out = (const float*)d_in[4];
    float* out = (float*)d_out;

    __half *qkvh, *qkvl, *xh, *xl, *wq16, *wo16, *ctxh, *ctxl;
    cudaGetSymbolAddress((void**)&qkvh, g_qkvh);
    cudaGetSymbolAddress((void**)&qkvl, g_qkvl);
    cudaGetSymbolAddress((void**)&xh,   g_xh);
    cudaGetSymbolAddress((void**)&xl,   g_xl);
    cudaGetSymbolAddress((void**)&wq16, g_wq16);
    cudaGetSymbolAddress((void**)&wo16, g_wo16);
    cudaGetSymbolAddress((void**)&ctxh, g_ctxh);
    cudaGetSymbolAddress((void**)&ctxl, g_ctxl);

    cudaFuncSetAttribute((const void*)hsgemm<true, 2>,
                         cudaFuncAttributeMaxDynamicSharedMemorySize, GEMM_SMEM);
    cudaFuncSetAttribute((const void*)hsgemm<true, 1>,
                         cudaFuncAttributeMaxDynamicSharedMemorySize, GEMM_SMEM);
    cudaFuncSetAttribute((const void*)hsgemm<false, 2>,
                         cudaFuncAttributeMaxDynamicSharedMemorySize, GEMM_SMEM);
    cudaFuncSetAttribute(attn_tc, cudaFuncAttributeMaxDynamicSharedMemorySize, ATT_SMEM);

    // 0) x -> fp16 hi/lo; weights -> fp16
    {
        int n4 = MROWS * EMBED / 4;
        splith_kernel<<<(n4 + 255) / 256, 256>>>(x, xh, xl, n4);
        n4 = EMBED * QKV_N / 4;
        cvth_kernel<<<(n4 + 255) / 256, 256>>>(w_qkv, wq16, n4);
        n4 = EMBED * EMBED / 4;
        cvth_kernel<<<(n4 + 255) / 256, 256>>>(w_out, wo16, n4);
    }

    // 1a) Q columns [0,1024): 2-term (exact)
    {
        dim3 grid(EMBED / BN, MROWS / BM);          // 8 x 64
        hsgemm<true, 2><<<grid, 256, GEMM_SMEM>>>(MROWS, QKV_N, EMBED, 0,
                                                  xh, xl, wq16, b_qkv,
                                                  nullptr, qkvh, qkvl);
    }
    // 1b) K/V columns [1024,3072): 1-term (hi only)
    {
        dim3 grid(2 * EMBED / BN, MROWS / BM);      // 16 x 64
        hsgemm<true, 1><<<grid, 256, GEMM_SMEM>>>(MROWS, QKV_N, EMBED, EMBED,
                                                  xh, xl, wq16, b_qkv,
                                                  nullptr, qkvh, qkvl);
    }
    // 2) Tensor-core attention -> fp16 hi/lo ctx
    {
        dim3 grid(SEQ / 64, HEADS, BATCH);
        attn_tc<<<grid, 128, ATT_SMEM>>>(qkvh, qkvl, ctxh, ctxl);
    }
    // 3) Output projection: full 2-term (output-critical)
    {
        dim3 grid(EMBED / BN, MROWS / BM);
        hsgemm<false, 2><<<grid, 256, GEMM_SMEM>>>(MROWS, EMBED, EMBED, 0,
                                                   ctxh, ctxl, wo16, b_out,
                                                   out, nullptr, nullptr);
    }
}

// round 15
// speedup vs baseline: 1.2018x; 1.0699x over previous
#include <cuda_runtime.h>
#include <cuda_bf16.h>
#include <cuda_fp16.h>
#include <cstdint>

#define BATCH   4
#define SEQ     2048
#define EMBED   1024
#define HEADS   16
#define HDIM    64
#define NGLOBAL 4
#define WINDOW  256

#define MROWS   (BATCH * SEQ)          // 8192
#define QKV_N   (3 * EMBED)            // 3072

// ---------------------------------------------------------------------------
// Scratch (device globals: allocation-guard-safe)
// ---------------------------------------------------------------------------
__device__ __half g_qkvh[(size_t)MROWS * QKV_N];   // fp16 hi (attn input)
__device__ __half g_qkvl[(size_t)MROWS * QKV_N];   // fp16 lo (Q cols only read)
__device__ __half g_xh  [(size_t)MROWS * EMBED];   // fp16 hi
__device__ __half g_xl  [(size_t)MROWS * EMBED];   // fp16 lo
__device__ __half g_wq16[(size_t)EMBED * QKV_N];   // fp16 weights
__device__ __half g_wo16[(size_t)EMBED * EMBED];
__device__ __half g_ctxh[(size_t)MROWS * EMBED];   // fp16 hi
__device__ __half g_ctxl[(size_t)MROWS * EMBED];   // fp16 lo

// ---------------------------------------------------------------------------
// Helpers
// ---------------------------------------------------------------------------
__device__ __forceinline__ void cp16(uint32_t dst, const void* src) {
    asm volatile("cp.async.cg.shared.global [%0], [%1], 16;\n"
                 :: "r"(dst), "l"(src));
}
__device__ __forceinline__ void ldsm4(uint32_t& r0, uint32_t& r1,
                                      uint32_t& r2, uint32_t& r3, uint32_t a) {
    asm volatile("ldmatrix.sync.aligned.m8n8.x4.shared.b16 {%0,%1,%2,%3},[%4];\n"
                 : "=r"(r0), "=r"(r1), "=r"(r2), "=r"(r3) : "r"(a));
}
__device__ __forceinline__ void ldsm4t(uint32_t& r0, uint32_t& r1,
                                       uint32_t& r2, uint32_t& r3, uint32_t a) {
    asm volatile("ldmatrix.sync.aligned.m8n8.x4.trans.shared.b16 {%0,%1,%2,%3},[%4];\n"
                 : "=r"(r0), "=r"(r1), "=r"(r2), "=r"(r3) : "r"(a));
}
// fp16 mma
__device__ __forceinline__ void mma16816h(float* c, const uint32_t* a,
                                          const uint32_t* b) {
    asm volatile(
        "mma.sync.aligned.m16n8k16.row.col.f32.f16.f16.f32 "
        "{%0,%1,%2,%3},{%4,%5,%6,%7},{%8,%9},{%0,%1,%2,%3};\n"
        : "+f"(c[0]), "+f"(c[1]), "+f"(c[2]), "+f"(c[3])
        : "r"(a[0]), "r"(a[1]), "r"(a[2]), "r"(a[3]), "r"(b[0]), "r"(b[1]));
}
// fp16 hi/lo packed split
__device__ __forceinline__ void split2h(float a, float b,
                                        uint32_t& h, uint32_t& l) {
    __half ha = __float2half_rn(a), hb = __float2half_rn(b);
    __half la = __float2half_rn(a - __half2float(ha));
    __half lb = __float2half_rn(b - __half2float(hb));
    h = ((uint32_t)__half_as_ushort(hb) << 16) | __half_as_ushort(ha);
    l = ((uint32_t)__half_as_ushort(lb) << 16) | __half_as_ushort(la);
}
// pack two fp32 -> fp16x2 (hi only)
__device__ __forceinline__ uint32_t pack2h(float a, float b) {
    __half2 p = __floats2half2_rn(a, b);
    return *(uint32_t*)&p;
}

// ---------------------------------------------------------------------------
// Prep kernels
// ---------------------------------------------------------------------------
__global__ void splith_kernel(const float* __restrict__ src,
                              __half* __restrict__ hi,
                              __half* __restrict__ lo, int n4)
{
    int i = blockIdx.x * blockDim.x + threadIdx.x;
    if (i >= n4) return;
    float4 v = ((const float4*)src)[i];
    uint32_t h0, l0, h1, l1;
    split2h(v.x, v.y, h0, l0);
    split2h(v.z, v.w, h1, l1);
    ((uint2*)hi)[i] = make_uint2(h0, h1);
    ((uint2*)lo)[i] = make_uint2(l0, l1);
}

__global__ void cvth_kernel(const float* __restrict__ src,
                            __half* __restrict__ dst, int n4)
{
    int i = blockIdx.x * blockDim.x + threadIdx.x;
    if (i >= n4) return;
    float4 v = ((const float4*)src)[i];
    ((uint2*)dst)[i] = make_uint2(pack2h(v.x, v.y), pack2h(v.z, v.w));
}

// ---------------------------------------------------------------------------
// fp16 tensor-core GEMM: C[:, n0 + bn*BN ...] = (Ah[+Al]) @ B + bias.
// TERMS compile-time (1|2): 1-term has Al loads/ldsm/mma dead-code-removed.
// SPLIT: fp16 hi/lo C, else fp32 C. n0 = column offset of this launch.
// ---------------------------------------------------------------------------
#define BM 128
#define BN 128
#define BKK 64
#define ALD (BKK + 8)
#define BLD (BN + 8)
#define OFF_AH 0
#define OFF_AL (BM * ALD)
#define OFF_B  (2 * BM * ALD)
#define STAGE_H (2 * BM * ALD + BKK * BLD)
#define GEMM_SMEM (2 * STAGE_H * 2)

template <bool SPLIT, int TERMS>
__global__ __launch_bounds__(256, 2) void hsgemm(
    int M, int N, int K, int n0,
    const __half* __restrict__ Ah, const __half* __restrict__ Al,
    const __half* __restrict__ B16,
    const float* __restrict__ bias, float* __restrict__ C,
    __half* __restrict__ Ch, __half* __restrict__ Cl)
{
    extern __shared__ __half sm[];
    const int tid = threadIdx.x;
    const int bm = blockIdx.y;
    const int cb = n0 + blockIdx.x * BN;       // global column base
    const int wid = tid >> 5, lane = tid & 31;
    const int wm = (wid >> 1) * 32, wn = (wid & 1) * 64;

    const uint32_t smem_base = (uint32_t)__cvta_generic_to_shared(sm);

    float acc[2][8][4];
    #pragma unroll
    for (int mi = 0; mi < 2; mi++)
        #pragma unroll
        for (int nj = 0; nj < 8; nj++)
            #pragma unroll
            for (int r = 0; r < 4; r++) acc[mi][nj][r] = 0.f;

    const int NK = K / BKK;

    auto load_stage = [&](int s, int kt) {
        const uint32_t base = smem_base + s * (STAGE_H * 2);
        const int k0 = kt * BKK;
        #pragma unroll
        for (int i = 0; i < 4; i++) {
            int idx = tid + i * 256;
            int r = idx >> 3, c = (idx & 7) << 3;
            size_t aoff = (size_t)(bm * BM + r) * K + k0 + c;
            cp16(base + (OFF_AH + r * ALD + c) * 2, Ah + aoff);
            if (TERMS == 2)
                cp16(base + (OFF_AL + r * ALD + c) * 2, Al + aoff);
            int rb = idx >> 4, cbk = (idx & 15) << 3;
            size_t boff = (size_t)(k0 + rb) * N + cb + cbk;
            cp16(base + (OFF_B + rb * BLD + cbk) * 2, B16 + boff);
        }
        asm volatile("cp.async.commit_group;\n");
    };

    load_stage(0, 0);

    for (int kt = 0; kt < NK; kt++) {
        if (kt + 1 < NK) {
            load_stage((kt + 1) & 1, kt + 1);
            asm volatile("cp.async.wait_group 1;\n");
        } else {
            asm volatile("cp.async.wait_group 0;\n");
        }
        __syncthreads();

        const uint32_t base = smem_base + (kt & 1) * (STAGE_H * 2);

        #pragma unroll
        for (int ks = 0; ks < 4; ks++) {
            const int k = ks * 16;
            uint32_t ah[2][4], al[2][4];
            #pragma unroll
            for (int mi = 0; mi < 2; mi++) {
                int row = wm + mi * 16 + (lane & 15);
                int col = k + (lane >> 4) * 8;
                ldsm4(ah[mi][0], ah[mi][1], ah[mi][2], ah[mi][3],
                      base + (OFF_AH + row * ALD + col) * 2);
                if (TERMS == 2)
                    ldsm4(al[mi][0], al[mi][1], al[mi][2], al[mi][3],
                          base + (OFF_AL + row * ALD + col) * 2);
            }
            uint32_t bf[4][4];
            #pragma unroll
            for (int ng = 0; ng < 4; ng++) {
                int row = k + (lane & 15);
                int col = wn + ng * 16 + (lane >> 4) * 8;
                ldsm4t(bf[ng][0], bf[ng][1], bf[ng][2], bf[ng][3],
                       base + (OFF_B + row * BLD + col) * 2);
            }
            #pragma unroll
            for (int mi = 0; mi < 2; mi++) {
                #pragma unroll
                for (int nj = 0; nj < 8; nj++) {
                    const uint32_t* bp = &bf[nj >> 1][(nj & 1) * 2];
                    mma16816h(acc[mi][nj], ah[mi], bp);
                    if (TERMS == 2) mma16816h(acc[mi][nj], al[mi], bp);
                }
            }
        }
        __syncthreads();
    }

    #pragma unroll
    for (int mi = 0; mi < 2; mi++) {
        #pragma unroll
        for (int nj = 0; nj < 8; nj++) {
            int r0 = bm * BM + wm + mi * 16 + (lane >> 2);
            int c0 = cb + wn + nj * 8 + (lane & 3) * 2;
            float b0 = bias[c0], b1 = bias[c0 + 1];
            float v00 = acc[mi][nj][0] + b0, v01 = acc[mi][nj][1] + b1;
            float v10 = acc[mi][nj][2] + b0, v11 = acc[mi][nj][3] + b1;
            if (SPLIT) {
                uint32_t hp, lp;
                split2h(v00, v01, hp, lp);
                *(uint32_t*)&Ch[(size_t)r0 * N + c0] = hp;
                *(uint32_t*)&Cl[(size_t)r0 * N + c0] = lp;
                split2h(v10, v11, hp, lp);
                *(uint32_t*)&Ch[(size_t)(r0 + 8) * N + c0] = hp;
                *(uint32_t*)&Cl[(size_t)(r0 + 8) * N + c0] = lp;
            } else {
                *(float2*)&C[(size_t)r0 * N + c0]       = make_float2(v00, v01);
                *(float2*)&C[(size_t)(r0 + 8) * N + c0] = make_float2(v10, v11);
            }
        }
    }
}

// ---------------------------------------------------------------------------
// Tensor-core flash attention: CTA = (64-query block, head, batch), 4 warps.
// S = (Qh+Ql)Kh (2-term). O += Ph Vh (1-term: P hi only — Pl correction is
// below Vh's own fp16 noise floor). ctx out fp16 hi/lo.
// ---------------------------------------------------------------------------
#define AP 72
#define ATT_SQH 0
#define ATT_SQL (64 * AP)
#define ATT_STAGE0 (2 * 64 * AP)
#define ATT_STAGE_SZ (2 * 64 * AP)        // K hi + V hi only
#define ATT_KH 0
#define ATT_VH (64 * AP)
#define ATT_SMEM ((2 * 64 * AP + 2 * 2 * 64 * AP) * 2)   // 55296 bytes

__global__ __launch_bounds__(128) void attn_tc(
    const __half* __restrict__ qh_g,
    const __half* __restrict__ ql_g,
    __half* __restrict__ ctxh,
    __half* __restrict__ ctxl)
{
    extern __shared__ __half smb[];
    const uint32_t sb = (uint32_t)__cvta_generic_to_shared(smb);
    const int qb = blockIdx.x, h = blockIdx.y, b = blockIdx.z;
    const int qs = qb * 64;
    const bool isg = (h < NGLOBAL);
    const int tid = threadIdx.x, lane = tid & 31, warp = tid >> 5;
    const int wq = warp * 16;
    const size_t rowbase = (size_t)(b * SEQ) * QKV_N;
    const float NEG_INF = __int_as_float(0xff800000u);

    #pragma unroll
    for (int i = 0; i < 4; i++) {
        int idx = tid + i * 128;
        int r = idx >> 3, c8 = (idx & 7) * 8;
        size_t src = rowbase + (size_t)(qs + r) * QKV_N + h * HDIM + c8;
        cp16(sb + (ATT_SQH + r * AP + c8) * 2, qh_g + src);
        cp16(sb + (ATT_SQL + r * AP + c8) * 2, ql_g + src);
    }
    asm volatile("cp.async.commit_group;\n");

    const int kb0 = isg ? 0 : max(0, qb - 4);

    auto load_kv = [&](int kb, int s) {
        const uint32_t base = sb + (ATT_STAGE0 + s * ATT_STAGE_SZ) * 2;
        const int ks = kb * 64;
        #pragma unroll
        for (int i = 0; i < 4; i++) {
            int idx = tid + i * 128;
            int r = idx >> 3, c8 = (idx & 7) * 8;
            size_t src = rowbase + (size_t)(ks + r) * QKV_N + EMBED + h * HDIM + c8;
            cp16(base + (ATT_KH + r * AP + c8) * 2, qh_g + src);
            cp16(base + (ATT_VH + r * AP + c8) * 2, qh_g + src + EMBED);
        }
        asm volatile("cp.async.commit_group;\n");
    };

    load_kv(kb0, 0);

    float m0 = -1e30f, m1 = -1e30f, l0 = 0.f, l1 = 0.f;
    float O[8][4];
    #pragma unroll
    for (int nj = 0; nj < 8; nj++)
        #pragma unroll
        for (int r = 0; r < 4; r++) O[nj][r] = 0.f;

    uint32_t qfh[4][4], qfl[4][4];
    bool qloaded = false;

    for (int kb = kb0; kb <= qb; kb++) {
        const int s = (kb - kb0) & 1;
        const int ks = kb * 64;
        __syncthreads();
        if (kb < qb) {
            load_kv(kb + 1, s ^ 1);
            asm volatile("cp.async.wait_group 1;\n");
        } else {
            asm volatile("cp.async.wait_group 0;\n");
        }
        __syncthreads();

        if (!qloaded) {
            qloaded = true;
            #pragma unroll
            for (int kt = 0; kt < 4; kt++) {
                uint32_t a = sb + (ATT_SQH + (wq + (lane & 15)) * AP
                                   + kt * 16 + 8 * (lane >> 4)) * 2;
                ldsm4(qfh[kt][0], qfh[kt][1], qfh[kt][2], qfh[kt][3], a);
                ldsm4(qfl[kt][0], qfl[kt][1], qfl[kt][2], qfl[kt][3],
                      a + (ATT_SQL - ATT_SQH) * 2);
            }
        }

        const uint32_t kbase = sb + (ATT_STAGE0 + s * ATT_STAGE_SZ) * 2;

        // ---- S = (Qh+Ql) Kh ----
        float sf[8][4];
        #pragma unroll
        for (int nj = 0; nj < 8; nj++)
            #pragma unroll
            for (int r = 0; r < 4; r++) sf[nj][r] = 0.f;

        #pragma unroll
        for (int kt = 0; kt < 4; kt++) {
            #pragma unroll
            for (int ng = 0; ng < 4; ng++) {
                uint32_t kh[4];
                uint32_t a = kbase + ((ng * 16 + (lane & 15)) * AP
                                      + kt * 16 + 8 * (lane >> 4)) * 2;
                ldsm4(kh[0], kh[1], kh[2], kh[3], a + ATT_KH * 2);
                uint32_t bh0[2] = {kh[0], kh[2]}, bh1[2] = {kh[1], kh[3]};
                mma16816h(sf[2 * ng],     qfh[kt], bh0);
                mma16816h(sf[2 * ng],     qfl[kt], bh0);
                mma16816h(sf[2 * ng + 1], qfh[kt], bh1);
                mma16816h(sf[2 * ng + 1], qfl[kt], bh1);
            }
        }
        #pragma unroll
        for (int nj = 0; nj < 8; nj++)
            #pragma unroll
            for (int r = 0; r < 4; r++) sf[nj][r] *= 0.125f;

        // ---- mask ----
        const int i0 = qs + wq + (lane >> 2);
        const int i1 = i0 + 8;
        const int mode = (kb == qb) ? 1 : ((!isg && (qb - kb) == 4) ? 2 : 0);
        if (mode == 1) {
            #pragma unroll
            for (int nj = 0; nj < 8; nj++) {
                int j0 = ks + nj * 8 + (lane & 3) * 2, j1 = j0 + 1;
                if (j0 > i0) sf[nj][0] = NEG_INF;
                if (j1 > i0) sf[nj][1] = NEG_INF;
                if (j0 > i1) sf[nj][2] = NEG_INF;
                if (j1 > i1) sf[nj][3] = NEG_INF;
            }
        } else if (mode == 2) {
            #pragma unroll
            for (int nj = 0; nj < 8; nj++) {
                int j0 = ks + nj * 8 + (lane & 3) * 2, j1 = j0 + 1;
                if (i0 - j0 > WINDOW) sf[nj][0] = NEG_INF;
                if (i0 - j1 > WINDOW) sf[nj][1] = NEG_INF;
                if (i1 - j0 > WINDOW) sf[nj][2] = NEG_INF;
                if (i1 - j1 > WINDOW) sf[nj][3] = NEG_INF;
            }
        }

        // ---- online softmax ----
        float mx0 = -1e30f, mx1 = -1e30f;
        #pragma unroll
        for (int nj = 0; nj < 8; nj++) {
            mx0 = fmaxf(mx0, fmaxf(sf[nj][0], sf[nj][1]));
            mx1 = fmaxf(mx1, fmaxf(sf[nj][2], sf[nj][3]));
        }
        mx0 = fmaxf(mx0, __shfl_xor_sync(0xffffffffu, mx0, 1));
        mx0 = fmaxf(mx0, __shfl_xor_sync(0xffffffffu, mx0, 2));
        mx1 = fmaxf(mx1, __shfl_xor_sync(0xffffffffu, mx1, 1));
        mx1 = fmaxf(mx1, __shfl_xor_sync(0xffffffffu, mx1, 2));
        const float mn0 = fmaxf(m0, mx0), mn1 = fmaxf(m1, mx1);
        float s0 = 0.f, s1 = 0.f;
        #pragma unroll
        for (int nj = 0; nj < 8; nj++) {
            sf[nj][0] = __expf(sf[nj][0] - mn0);
            sf[nj][1] = __expf(sf[nj][1] - mn0);
            sf[nj][2] = __expf(sf[nj][2] - mn1);
            sf[nj][3] = __expf(sf[nj][3] - mn1);
            s0 += sf[nj][0] + sf[nj][1];
            s1 += sf[nj][2] + sf[nj][3];
        }
        s0 += __shfl_xor_sync(0xffffffffu, s0, 1);
        s0 += __shfl_xor_sync(0xffffffffu, s0, 2);
        s1 += __shfl_xor_sync(0xffffffffu, s1, 1);
        s1 += __shfl_xor_sync(0xffffffffu, s1, 2);
        const float a0 = __expf(m0 - mn0), a1 = __expf(m1 - mn1);
        l0 = l0 * a0 + s0; l1 = l1 * a1 + s1;
        m0 = mn0; m1 = mn1;
        #pragma unroll
        for (int nj = 0; nj < 8; nj++) {
            O[nj][0] *= a0; O[nj][1] *= a0;
            O[nj][2] *= a1; O[nj][3] *= a1;
        }

        // ---- O += Ph Vh (1-term) ----
        #pragma unroll
        for (int kt = 0; kt < 4; kt++) {
            uint32_t pah[4];
            pah[0] = pack2h(sf[2 * kt][0],     sf[2 * kt][1]);
            pah[1] = pack2h(sf[2 * kt][2],     sf[2 * kt][3]);
            pah[2] = pack2h(sf[2 * kt + 1][0], sf[2 * kt + 1][1]);
            pah[3] = pack2h(sf[2 * kt + 1][2], sf[2 * kt + 1][3]);
            #pragma unroll
            for (int ng = 0; ng < 4; ng++) {
                uint32_t vh[4];
                uint32_t a = kbase + ((kt * 16 + (lane & 15)) * AP
                                      + ng * 16 + 8 * (lane >> 4)) * 2;
                ldsm4t(vh[0], vh[1], vh[2], vh[3], a + ATT_VH * 2);
                mma16816h(O[2 * ng],     pah, &vh[0]);
                mma16816h(O[2 * ng + 1], pah, &vh[2]);
            }
        }
    }

    const float inv0 = 1.f / l0, inv1 = 1.f / l1;
    const int r0g = qs + wq + (lane >> 2);
    const size_t base0 = ((size_t)(b * SEQ + r0g)) * EMBED + h * HDIM;
    #pragma unroll
    for (int nj = 0; nj < 8; nj++) {
        const int c = nj * 8 + (lane & 3) * 2;
        uint32_t hp, lp;
        split2h(O[nj][0] * inv0, O[nj][1] * inv0, hp, lp);
        *(uint32_t*)&ctxh[base0 + c] = hp;
        *(uint32_t*)&ctxl[base0 + c] = lp;
        split2h(O[nj][2] * inv1, O[nj][3] * inv1, hp, lp);
        *(uint32_t*)&ctxh[base0 + (size_t)8 * EMBED + c] = hp;
        *(uint32_t*)&ctxl[base0 + (size_t)8 * EMBED + c] = lp;
    }
}

// ---------------------------------------------------------------------------
// Launch
// ---------------------------------------------------------------------------
extern "C" void kernel_launch(void* const* d_in, const int* in_sizes, int n_in,
                              void* d_out, int out_size)
{
    const float* x     = (const float*)d_in[0];
    const float* w_qkv = (const float*)d_in[1];
    const float* b_qkv = (const float*)d_in[2];
    const float* w_out = (const float*)d_in[3];
    const float* b_out = (const float*)d_in[4];
    float* out = (float*)d_out;

    __half *qkvh, *qkvl, *xh, *xl, *wq16, *wo16, *ctxh, *ctxl;
    cudaGetSymbolAddress((void**)&qkvh, g_qkvh);
    cudaGetSymbolAddress((void**)&qkvl, g_qkvl);
    cudaGetSymbolAddress((void**)&xh,   g_xh);
    cudaGetSymbolAddress((void**)&xl,   g_xl);
    cudaGetSymbolAddress((void**)&wq16, g_wq16);
    cudaGetSymbolAddress((void**)&wo16, g_wo16);
    cudaGetSymbolAddress((void**)&ctxh, g_ctxh);
    cudaGetSymbolAddress((void**)&ctxl, g_ctxl);

    cudaFuncSetAttribute((const void*)hsgemm<true, 2>,
                         cudaFuncAttributeMaxDynamicSharedMemorySize, GEMM_SMEM);
    cudaFuncSetAttribute((const void*)hsgemm<true, 1>,
                         cudaFuncAttributeMaxDynamicSharedMemorySize, GEMM_SMEM);
    cudaFuncSetAttribute((const void*)hsgemm<false, 2>,
                         cudaFuncAttributeMaxDynamicSharedMemorySize, GEMM_SMEM);
    cudaFuncSetAttribute(attn_tc, cudaFuncAttributeMaxDynamicSharedMemorySize, ATT_SMEM);

    // 0) x -> fp16 hi/lo; weights -> fp16
    {
        int n4 = MROWS * EMBED / 4;
        splith_kernel<<<(n4 + 255) / 256, 256>>>(x, xh, xl, n4);
        n4 = EMBED * QKV_N / 4;
        cvth_kernel<<<(n4 + 255) / 256, 256>>>(w_qkv, wq16, n4);
        n4 = EMBED * EMBED / 4;
        cvth_kernel<<<(n4 + 255) / 256, 256>>>(w_out, wo16, n4);
    }

    // 1a) Q columns [0,1024): 2-term (exact)
    {
        dim3 grid(EMBED / BN, MROWS / BM);          // 8 x 64
        hsgemm<true, 2><<<grid, 256, GEMM_SMEM>>>(MROWS, QKV_N, EMBED, 0,
                                                  xh, xl, wq16, b_qkv,
                                                  nullptr, qkvh, qkvl);
    }
    // 1b) K/V columns [1024,3072): 1-term (hi only)
    {
        dim3 grid(2 * EMBED / BN, MROWS / BM);      // 16 x 64
        hsgemm<true, 1><<<grid, 256, GEMM_SMEM>>>(MROWS, QKV_N, EMBED, EMBED,
                                                  xh, xl, wq16, b_qkv,
                                                  nullptr, qkvh, qkvl);
    }
    // 2) Tensor-core attention -> fp16 hi/lo ctx
    {
        dim3 grid(SEQ / 64, HEADS, BATCH);
        attn_tc<<<grid, 128, ATT_SMEM>>>(qkvh, qkvl, ctxh, ctxl);
    }
    // 3) Output projection: full 2-term (output-critical)
    {
        dim3 grid(EMBED / BN, MROWS / BM);
        hsgemm<false, 2><<<grid, 256, GEMM_SMEM>>>(MROWS, EMBED, EMBED, 0,
                                                   ctxh, ctxl, wo16, b_out,
                                                   out, nullptr, nullptr);
    }
}

// round 16
// speedup vs baseline: 1.4900x; 1.2399x over previous
#include <cuda_runtime.h>
#include <cuda_bf16.h>
#include <cuda_fp16.h>
#include <cstdint>

#define BATCH   4
#define SEQ     2048
#define EMBED   1024
#define HEADS   16
#define HDIM    64
#define NGLOBAL 4
#define WINDOW  256

#define MROWS   (BATCH * SEQ)          // 8192
#define QKV_N   (3 * EMBED)            // 3072

// ---------------------------------------------------------------------------
// Scratch (device globals: allocation-guard-safe)
// ---------------------------------------------------------------------------
__device__ __half g_qkv16[(size_t)MROWS * QKV_N];  // fp16 qkv (Q pre-scaled 0.125)
__device__ __half g_x16 [(size_t)MROWS * EMBED];   // fp16 x
__device__ __half g_wq16[(size_t)EMBED * QKV_N];   // fp16 weights
__device__ __half g_wo16[(size_t)EMBED * EMBED];
__device__ __half g_ctxh[(size_t)MROWS * EMBED];   // fp16 hi
__device__ __half g_ctxl[(size_t)MROWS * EMBED];   // fp16 lo

// ---------------------------------------------------------------------------
// Helpers
// ---------------------------------------------------------------------------
__device__ __forceinline__ void cp16(uint32_t dst, const void* src) {
    asm volatile("cp.async.cg.shared.global [%0], [%1], 16;\n"
                 :: "r"(dst), "l"(src));
}
__device__ __forceinline__ void ldsm4(uint32_t& r0, uint32_t& r1,
                                      uint32_t& r2, uint32_t& r3, uint32_t a) {
    asm volatile("ldmatrix.sync.aligned.m8n8.x4.shared.b16 {%0,%1,%2,%3},[%4];\n"
                 : "=r"(r0), "=r"(r1), "=r"(r2), "=r"(r3) : "r"(a));
}
__device__ __forceinline__ void ldsm4t(uint32_t& r0, uint32_t& r1,
                                       uint32_t& r2, uint32_t& r3, uint32_t a) {
    asm volatile("ldmatrix.sync.aligned.m8n8.x4.trans.shared.b16 {%0,%1,%2,%3},[%4];\n"
                 : "=r"(r0), "=r"(r1), "=r"(r2), "=r"(r3) : "r"(a));
}
// fp16 mma
__device__ __forceinline__ void mma16816h(float* c, const uint32_t* a,
                                          const uint32_t* b) {
    asm volatile(
        "mma.sync.aligned.m16n8k16.row.col.f32.f16.f16.f32 "
        "{%0,%1,%2,%3},{%4,%5,%6,%7},{%8,%9},{%0,%1,%2,%3};\n"
        : "+f"(c[0]), "+f"(c[1]), "+f"(c[2]), "+f"(c[3])
        : "r"(a[0]), "r"(a[1]), "r"(a[2]), "r"(a[3]), "r"(b[0]), "r"(b[1]));
}
// fp16 hi/lo packed split
__device__ __forceinline__ void split2h(float a, float b,
                                        uint32_t& h, uint32_t& l) {
    __half ha = __float2half_rn(a), hb = __float2half_rn(b);
    __half la = __float2half_rn(a - __half2float(ha));
    __half lb = __float2half_rn(b - __half2float(hb));
    h = ((uint32_t)__half_as_ushort(hb) << 16) | __half_as_ushort(ha);
    l = ((uint32_t)__half_as_ushort(lb) << 16) | __half_as_ushort(la);
}
// pack two fp32 -> fp16x2
__device__ __forceinline__ uint32_t pack2h(float a, float b) {
    __half2 p = __floats2half2_rn(a, b);
    return *(uint32_t*)&p;
}

// ---------------------------------------------------------------------------
// Prep kernel: fp32 -> fp16
// ---------------------------------------------------------------------------
__global__ void cvth_kernel(const float* __restrict__ src,
                            __half* __restrict__ dst, int n4)
{
    int i = blockIdx.x * blockDim.x + threadIdx.x;
    if (i >= n4) return;
    float4 v = ((const float4*)src)[i];
    ((uint2*)dst)[i] = make_uint2(pack2h(v.x, v.y), pack2h(v.z, v.w));
}

// ---------------------------------------------------------------------------
// fp16 tensor-core GEMM: C[:, n0 + bn*BN ...] = (Ah[+Al]) @ B + bias.
// TERMS compile-time (1|2). OMODE: 0 = fp32 out; 1 = fp16 out with per-CTA
// scale (columns < nsc get *0.125 — Q pre-scaling folded into epilogue).
// ---------------------------------------------------------------------------
#define BM 128
#define BN 128
#define BKK 64
#define ALD (BKK + 8)
#define BLD (BN + 8)
#define OFF_AH 0
#define OFF_AL (BM * ALD)
#define OFF_B  (2 * BM * ALD)
#define STAGE_H (2 * BM * ALD + BKK * BLD)
#define GEMM_SMEM (2 * STAGE_H * 2)

template <int OMODE, int TERMS>
__global__ __launch_bounds__(256, 2) void hsgemm(
    int M, int N, int K, int n0, int nsc,
    const __half* __restrict__ Ah, const __half* __restrict__ Al,
    const __half* __restrict__ B16,
    const float* __restrict__ bias, float* __restrict__ C,
    __half* __restrict__ Ch)
{
    extern __shared__ __half sm[];
    const int tid = threadIdx.x;
    const int bm = blockIdx.y;
    const int cb = n0 + blockIdx.x * BN;       // global column base
    const int wid = tid >> 5, lane = tid & 31;
    const int wm = (wid >> 1) * 32, wn = (wid & 1) * 64;

    const uint32_t smem_base = (uint32_t)__cvta_generic_to_shared(sm);

    float acc[2][8][4];
    #pragma unroll
    for (int mi = 0; mi < 2; mi++)
        #pragma unroll
        for (int nj = 0; nj < 8; nj++)
            #pragma unroll
            for (int r = 0; r < 4; r++) acc[mi][nj][r] = 0.f;

    const int NK = K / BKK;

    auto load_stage = [&](int s, int kt) {
        const uint32_t base = smem_base + s * (STAGE_H * 2);
        const int k0 = kt * BKK;
        #pragma unroll
        for (int i = 0; i < 4; i++) {
            int idx = tid + i * 256;
            int r = idx >> 3, c = (idx & 7) << 3;
            size_t aoff = (size_t)(bm * BM + r) * K + k0 + c;
            cp16(base + (OFF_AH + r * ALD + c) * 2, Ah + aoff);
            if (TERMS == 2)
                cp16(base + (OFF_AL + r * ALD + c) * 2, Al + aoff);
            int rb = idx >> 4, cbk = (idx & 15) << 3;
            size_t boff = (size_t)(k0 + rb) * N + cb + cbk;
            cp16(base + (OFF_B + rb * BLD + cbk) * 2, B16 + boff);
        }
        asm volatile("cp.async.commit_group;\n");
    };

    load_stage(0, 0);

    for (int kt = 0; kt < NK; kt++) {
        if (kt + 1 < NK) {
            load_stage((kt + 1) & 1, kt + 1);
            asm volatile("cp.async.wait_group 1;\n");
        } else {
            asm volatile("cp.async.wait_group 0;\n");
        }
        __syncthreads();

        const uint32_t base = smem_base + (kt & 1) * (STAGE_H * 2);

        #pragma unroll
        for (int ks = 0; ks < 4; ks++) {
            const int k = ks * 16;
            uint32_t ah[2][4], al[2][4];
            #pragma unroll
            for (int mi = 0; mi < 2; mi++) {
                int row = wm + mi * 16 + (lane & 15);
                int col = k + (lane >> 4) * 8;
                ldsm4(ah[mi][0], ah[mi][1], ah[mi][2], ah[mi][3],
                      base + (OFF_AH + row * ALD + col) * 2);
                if (TERMS == 2)
                    ldsm4(al[mi][0], al[mi][1], al[mi][2], al[mi][3],
                          base + (OFF_AL + row * ALD + col) * 2);
            }
            uint32_t bf[4][4];
            #pragma unroll
            for (int ng = 0; ng < 4; ng++) {
                int row = k + (lane & 15);
                int col = wn + ng * 16 + (lane >> 4) * 8;
                ldsm4t(bf[ng][0], bf[ng][1], bf[ng][2], bf[ng][3],
                       base + (OFF_B + row * BLD + col) * 2);
            }
            #pragma unroll
            for (int mi = 0; mi < 2; mi++) {
                #pragma unroll
                for (int nj = 0; nj < 8; nj++) {
                    const uint32_t* bp = &bf[nj >> 1][(nj & 1) * 2];
                    mma16816h(acc[mi][nj], ah[mi], bp);
                    if (TERMS == 2) mma16816h(acc[mi][nj], al[mi], bp);
                }
            }
        }
        __syncthreads();
    }

    const float cs = (OMODE == 1 && cb < nsc) ? 0.125f : 1.0f;
    #pragma unroll
    for (int mi = 0; mi < 2; mi++) {
        #pragma unroll
        for (int nj = 0; nj < 8; nj++) {
            int r0 = bm * BM + wm + mi * 16 + (lane >> 2);
            int c0 = cb + wn + nj * 8 + (lane & 3) * 2;
            float b0 = bias[c0], b1 = bias[c0 + 1];
            float v00 = (acc[mi][nj][0] + b0) * cs, v01 = (acc[mi][nj][1] + b1) * cs;
            float v10 = (acc[mi][nj][2] + b0) * cs, v11 = (acc[mi][nj][3] + b1) * cs;
            if (OMODE == 1) {
                *(uint32_t*)&Ch[(size_t)r0 * N + c0]       = pack2h(v00, v01);
                *(uint32_t*)&Ch[(size_t)(r0 + 8) * N + c0] = pack2h(v10, v11);
            } else {
                *(float2*)&C[(size_t)r0 * N + c0]       = make_float2(v00, v01);
                *(float2*)&C[(size_t)(r0 + 8) * N + c0] = make_float2(v10, v11);
            }
        }
    }
}

// ---------------------------------------------------------------------------
// Tensor-core flash attention: CTA = (64-query block, head, batch), 4 warps.
// All fp16 1-term: S = Qh Kh (Q pre-scaled), O += Ph Vh. ctx out fp16 hi/lo.
// ---------------------------------------------------------------------------
#define AP 72
#define ATT_SQ 0
#define ATT_STAGE0 (64 * AP)
#define ATT_STAGE_SZ (2 * 64 * AP)        // K + V
#define ATT_KH 0
#define ATT_VH (64 * AP)
#define ATT_SMEM ((64 * AP + 2 * 2 * 64 * AP) * 2)   // 46080 bytes

__global__ __launch_bounds__(128) void attn_tc(
    const __half* __restrict__ qkv,
    __half* __restrict__ ctxh,
    __half* __restrict__ ctxl)
{
    extern __shared__ __half smb[];
    const uint32_t sb = (uint32_t)__cvta_generic_to_shared(smb);
    const int qb = blockIdx.x, h = blockIdx.y, b = blockIdx.z;
    const int qs = qb * 64;
    const bool isg = (h < NGLOBAL);
    const int tid = threadIdx.x, lane = tid & 31, warp = tid >> 5;
    const int wq = warp * 16;
    const size_t rowbase = (size_t)(b * SEQ) * QKV_N;
    const float NEG_INF = __int_as_float(0xff800000u);

    // Q load (pre-scaled by 0.125 in GEMM1 epilogue)
    #pragma unroll
    for (int i = 0; i < 4; i++) {
        int idx = tid + i * 128;
        int r = idx >> 3, c8 = (idx & 7) * 8;
        size_t src = rowbase + (size_t)(qs + r) * QKV_N + h * HDIM + c8;
        cp16(sb + (ATT_SQ + r * AP + c8) * 2, qkv + src);
    }
    asm volatile("cp.async.commit_group;\n");

    const int kb0 = isg ? 0 : max(0, qb - 4);

    auto load_kv = [&](int kb, int s) {
        const uint32_t base = sb + (ATT_STAGE0 + s * ATT_STAGE_SZ) * 2;
        const int ks = kb * 64;
        #pragma unroll
        for (int i = 0; i < 4; i++) {
            int idx = tid + i * 128;
            int r = idx >> 3, c8 = (idx & 7) * 8;
            size_t src = rowbase + (size_t)(ks + r) * QKV_N + EMBED + h * HDIM + c8;
            cp16(base + (ATT_KH + r * AP + c8) * 2, qkv + src);
            cp16(base + (ATT_VH + r * AP + c8) * 2, qkv + src + EMBED);
        }
        asm volatile("cp.async.commit_group;\n");
    };

    load_kv(kb0, 0);

    float m0 = -1e30f, m1 = -1e30f, l0 = 0.f, l1 = 0.f;
    float O[8][4];
    #pragma unroll
    for (int nj = 0; nj < 8; nj++)
        #pragma unroll
        for (int r = 0; r < 4; r++) O[nj][r] = 0.f;

    uint32_t qf[4][4];
    bool qloaded = false;

    for (int kb = kb0; kb <= qb; kb++) {
        const int s = (kb - kb0) & 1;
        const int ks = kb * 64;
        __syncthreads();
        if (kb < qb) {
            load_kv(kb + 1, s ^ 1);
            asm volatile("cp.async.wait_group 1;\n");
        } else {
            asm volatile("cp.async.wait_group 0;\n");
        }
        __syncthreads();

        if (!qloaded) {
            qloaded = true;
            #pragma unroll
            for (int kt = 0; kt < 4; kt++) {
                uint32_t a = sb + (ATT_SQ + (wq + (lane & 15)) * AP
                                   + kt * 16 + 8 * (lane >> 4)) * 2;
                ldsm4(qf[kt][0], qf[kt][1], qf[kt][2], qf[kt][3], a);
            }
        }

        const uint32_t kbase = sb + (ATT_STAGE0 + s * ATT_STAGE_SZ) * 2;

        // ---- S = Qh Kh (1-term, pre-scaled) ----
        float sf[8][4];
        #pragma unroll
        for (int nj = 0; nj < 8; nj++)
            #pragma unroll
            for (int r = 0; r < 4; r++) sf[nj][r] = 0.f;

        #pragma unroll
        for (int kt = 0; kt < 4; kt++) {
            #pragma unroll
            for (int ng = 0; ng < 4; ng++) {
                uint32_t kh[4];
                uint32_t a = kbase + ((ng * 16 + (lane & 15)) * AP
                                      + kt * 16 + 8 * (lane >> 4)) * 2;
                ldsm4(kh[0], kh[1], kh[2], kh[3], a + ATT_KH * 2);
                uint32_t bh0[2] = {kh[0], kh[2]}, bh1[2] = {kh[1], kh[3]};
                mma16816h(sf[2 * ng],     qf[kt], bh0);
                mma16816h(sf[2 * ng + 1], qf[kt], bh1);
            }
        }

        // ---- mask ----
        const int i0 = qs + wq + (lane >> 2);
        const int i1 = i0 + 8;
        const int mode = (kb == qb) ? 1 : ((!isg && (qb - kb) == 4) ? 2 : 0);
        if (mode == 1) {
            #pragma unroll
            for (int nj = 0; nj < 8; nj++) {
                int j0 = ks + nj * 8 + (lane & 3) * 2, j1 = j0 + 1;
                if (j0 > i0) sf[nj][0] = NEG_INF;
                if (j1 > i0) sf[nj][1] = NEG_INF;
                if (j0 > i1) sf[nj][2] = NEG_INF;
                if (j1 > i1) sf[nj][3] = NEG_INF;
            }
        } else if (mode == 2) {
            #pragma unroll
            for (int nj = 0; nj < 8; nj++) {
                int j0 = ks + nj * 8 + (lane & 3) * 2, j1 = j0 + 1;
                if (i0 - j0 > WINDOW) sf[nj][0] = NEG_INF;
                if (i0 - j1 > WINDOW) sf[nj][1] = NEG_INF;
                if (i1 - j0 > WINDOW) sf[nj][2] = NEG_INF;
                if (i1 - j1 > WINDOW) sf[nj][3] = NEG_INF;
            }
        }

        // ---- online softmax ----
        float mx0 = -1e30f, mx1 = -1e30f;
        #pragma unroll
        for (int nj = 0; nj < 8; nj++) {
            mx0 = fmaxf(mx0, fmaxf(sf[nj][0], sf[nj][1]));
            mx1 = fmaxf(mx1, fmaxf(sf[nj][2], sf[nj][3]));
        }
        mx0 = fmaxf(mx0, __shfl_xor_sync(0xffffffffu, mx0, 1));
        mx0 = fmaxf(mx0, __shfl_xor_sync(0xffffffffu, mx0, 2));
        mx1 = fmaxf(mx1, __shfl_xor_sync(0xffffffffu, mx1, 1));
        mx1 = fmaxf(mx1, __shfl_xor_sync(0xffffffffu, mx1, 2));
        const float mn0 = fmaxf(m0, mx0), mn1 = fmaxf(m1, mx1);
        float s0 = 0.f, s1 = 0.f;
        #pragma unroll
        for (int nj = 0; nj < 8; nj++) {
            sf[nj][0] = __expf(sf[nj][0] - mn0);
            sf[nj][1] = __expf(sf[nj][1] - mn0);
            sf[nj][2] = __expf(sf[nj][2] - mn1);
            sf[nj][3] = __expf(sf[nj][3] - mn1);
            s0 += sf[nj][0] + sf[nj][1];
            s1 += sf[nj][2] + sf[nj][3];
        }
        s0 += __shfl_xor_sync(0xffffffffu, s0, 1);
        s0 += __shfl_xor_sync(0xffffffffu, s0, 2);
        s1 += __shfl_xor_sync(0xffffffffu, s1, 1);
        s1 += __shfl_xor_sync(0xffffffffu, s1, 2);
        const float a0 = __expf(m0 - mn0), a1 = __expf(m1 - mn1);
        l0 = l0 * a0 + s0; l1 = l1 * a1 + s1;
        m0 = mn0; m1 = mn1;
        #pragma unroll
        for (int nj = 0; nj < 8; nj++) {
            O[nj][0] *= a0; O[nj][1] *= a0;
            O[nj][2] *= a1; O[nj][3] *= a1;
        }

        // ---- O += Ph Vh (1-term) ----
        #pragma unroll
        for (int kt = 0; kt < 4; kt++) {
            uint32_t pah[4];
            pah[0] = pack2h(sf[2 * kt][0],     sf[2 * kt][1]);
            pah[1] = pack2h(sf[2 * kt][2],     sf[2 * kt][3]);
            pah[2] = pack2h(sf[2 * kt + 1][0], sf[2 * kt + 1][1]);
            pah[3] = pack2h(sf[2 * kt + 1][2], sf[2 * kt + 1][3]);
            #pragma unroll
            for (int ng = 0; ng < 4; ng++) {
                uint32_t vh[4];
                uint32_t a = kbase + ((kt * 16 + (lane & 15)) * AP
                                      + ng * 16 + 8 * (lane >> 4)) * 2;
                ldsm4t(vh[0], vh[1], vh[2], vh[3], a + ATT_VH * 2);
                mma16816h(O[2 * ng],     pah, &vh[0]);
                mma16816h(O[2 * ng + 1], pah, &vh[2]);
            }
        }
    }

    const float inv0 = 1.f / l0, inv1 = 1.f / l1;
    const int r0g = qs + wq + (lane >> 2);
    const size_t base0 = ((size_t)(b * SEQ + r0g)) * EMBED + h * HDIM;
    #pragma unroll
    for (int nj = 0; nj < 8; nj++) {
        const int c = nj * 8 + (lane & 3) * 2;
        uint32_t hp, lp;
        split2h(O[nj][0] * inv0, O[nj][1] * inv0, hp, lp);
        *(uint32_t*)&ctxh[base0 + c] = hp;
        *(uint32_t*)&ctxl[base0 + c] = lp;
        split2h(O[nj][2] * inv1, O[nj][3] * inv1, hp, lp);
        *(uint32_t*)&ctxh[base0 + (size_t)8 * EMBED + c] = hp;
        *(uint32_t*)&ctxl[base0 + (size_t)8 * EMBED + c] = lp;
    }
}

// ---------------------------------------------------------------------------
// Launch
// ---------------------------------------------------------------------------
extern "C" void kernel_launch(void* const* d_in, const int* in_sizes, int n_in,
                              void* d_out, int out_size)
{
    const float* x     = (const float*)d_in[0];
    const float* w_qkv = (const float*)d_in[1];
    const float* b_qkv = (const float*)d_in[2];
    const float* w_out = (const float*)d_in[3];
    const float* b_out = (const float*)d_in[4];
    float* out = (float*)d_out;

    __half *qkv16, *x16, *wq16, *wo16, *ctxh, *ctxl;
    cudaGetSymbolAddress((void**)&qkv16, g_qkv16);
    cudaGetSymbolAddress((void**)&x16,   g_x16);
    cudaGetSymbolAddress((void**)&wq16,  g_wq16);
    cudaGetSymbolAddress((void**)&wo16,  g_wo16);
    cudaGetSymbolAddress((void**)&ctxh,  g_ctxh);
    cudaGetSymbolAddress((void**)&ctxl,  g_ctxl);

    cudaFuncSetAttribute((const void*)hsgemm<1, 1>,
                         cudaFuncAttributeMaxDynamicSharedMemorySize, GEMM_SMEM);
    cudaFuncSetAttribute((const void*)hsgemm<0, 2>,
                         cudaFuncAttributeMaxDynamicSharedMemorySize, GEMM_SMEM);
    cudaFuncSetAttribute(attn_tc, cudaFuncAttributeMaxDynamicSharedMemorySize, ATT_SMEM);

    // 0) fp16 conversions
    {
        int n4 = MROWS * EMBED / 4;
        cvth_kernel<<<(n4 + 255) / 256, 256>>>(x, x16, n4);
        n4 = EMBED * QKV_N / 4;
        cvth_kernel<<<(n4 + 255) / 256, 256>>>(w_qkv, wq16, n4);
        n4 = EMBED * EMBED / 4;
        cvth_kernel<<<(n4 + 255) / 256, 256>>>(w_out, wo16, n4);
    }

    // 1) QKV projection: single 1-term launch; Q columns scaled by 0.125
    {
        dim3 grid(QKV_N / BN, MROWS / BM);          // 24 x 64
        hsgemm<1, 1><<<grid, 256, GEMM_SMEM>>>(MROWS, QKV_N, EMBED, 0, EMBED,
                                               x16, nullptr, wq16, b_qkv,
                                               nullptr, qkv16);
    }
    // 2) Tensor-core attention (all 1-term) -> fp16 hi/lo ctx
    {
        dim3 grid(SEQ / 64, HEADS, BATCH);
        attn_tc<<<grid, 128, ATT_SMEM>>>(qkv16, ctxh, ctxl);
    }
    // 3) Output projection: 2-term (output-critical) -> fp32 out
    {
        dim3 grid(EMBED / BN, MROWS / BM);          // 8 x 64
        hsgemm<0, 2><<<grid, 256, GEMM_SMEM>>>(MROWS, EMBED, EMBED, 0, 0,
                                               ctxh, ctxl, wo16, b_out,
                                               out, nullptr);
    }
}

// round 17
// speedup vs baseline: 1.7179x; 1.1529x over previous
#include <cuda_runtime.h>
#include <cuda_bf16.h>
#include <cuda_fp16.h>
#include <cstdint>

#define BATCH   4
#define SEQ     2048
#define EMBED   1024
#define HEADS   16
#define HDIM    64
#define NGLOBAL 4
#define WINDOW  256

#define MROWS   (BATCH * SEQ)          // 8192
#define QKV_N   (3 * EMBED)            // 3072

// ---------------------------------------------------------------------------
// Scratch (device globals: allocation-guard-safe)
// ---------------------------------------------------------------------------
__device__ __half g_qkv16[(size_t)MROWS * QKV_N];  // fp16 qkv (Q pre-scaled 0.125)
__device__ __half g_x16 [(size_t)MROWS * EMBED];   // fp16 x
__device__ __half g_wq16[(size_t)EMBED * QKV_N];   // fp16 weights
__device__ __half g_wo16[(size_t)EMBED * EMBED];
__device__ __half g_ctx16[(size_t)MROWS * EMBED];  // fp16 ctx (hi only)

// ---------------------------------------------------------------------------
// Helpers
// ---------------------------------------------------------------------------
__device__ __forceinline__ void cp16(uint32_t dst, const void* src) {
    asm volatile("cp.async.cg.shared.global [%0], [%1], 16;\n"
                 :: "r"(dst), "l"(src));
}
__device__ __forceinline__ void ldsm4(uint32_t& r0, uint32_t& r1,
                                      uint32_t& r2, uint32_t& r3, uint32_t a) {
    asm volatile("ldmatrix.sync.aligned.m8n8.x4.shared.b16 {%0,%1,%2,%3},[%4];\n"
                 : "=r"(r0), "=r"(r1), "=r"(r2), "=r"(r3) : "r"(a));
}
__device__ __forceinline__ void ldsm4t(uint32_t& r0, uint32_t& r1,
                                       uint32_t& r2, uint32_t& r3, uint32_t a) {
    asm volatile("ldmatrix.sync.aligned.m8n8.x4.trans.shared.b16 {%0,%1,%2,%3},[%4];\n"
                 : "=r"(r0), "=r"(r1), "=r"(r2), "=r"(r3) : "r"(a));
}
// fp16 mma
__device__ __forceinline__ void mma16816h(float* c, const uint32_t* a,
                                          const uint32_t* b) {
    asm volatile(
        "mma.sync.aligned.m16n8k16.row.col.f32.f16.f16.f32 "
        "{%0,%1,%2,%3},{%4,%5,%6,%7},{%8,%9},{%0,%1,%2,%3};\n"
        : "+f"(c[0]), "+f"(c[1]), "+f"(c[2]), "+f"(c[3])
        : "r"(a[0]), "r"(a[1]), "r"(a[2]), "r"(a[3]), "r"(b[0]), "r"(b[1]));
}
// pack two fp32 -> fp16x2
__device__ __forceinline__ uint32_t pack2h(float a, float b) {
    __half2 p = __floats2half2_rn(a, b);
    return *(uint32_t*)&p;
}

// ---------------------------------------------------------------------------
// Prep kernel: fp32 -> fp16
// ---------------------------------------------------------------------------
__global__ void cvth_kernel(const float* __restrict__ src,
                            __half* __restrict__ dst, int n4)
{
    int i = blockIdx.x * blockDim.x + threadIdx.x;
    if (i >= n4) return;
    float4 v = ((const float4*)src)[i];
    ((uint2*)dst)[i] = make_uint2(pack2h(v.x, v.y), pack2h(v.z, v.w));
}

// ---------------------------------------------------------------------------
// fp16 tensor-core GEMM: C[:, n0 + bn*BN ...] = (Ah[+Al]) @ B + bias.
// TERMS compile-time (1|2). OMODE: 0 = fp32 out; 1 = fp16 out with per-CTA
// scale (columns < nsc get *0.125 — Q pre-scaling folded into epilogue).
// ---------------------------------------------------------------------------
#define BM 128
#define BN 128
#define BKK 64
#define ALD (BKK + 8)
#define BLD (BN + 8)
#define OFF_AH 0
#define OFF_AL (BM * ALD)
#define OFF_B  (2 * BM * ALD)
#define STAGE_H (2 * BM * ALD + BKK * BLD)
#define GEMM_SMEM (2 * STAGE_H * 2)

template <int OMODE, int TERMS>
__global__ __launch_bounds__(256, 2) void hsgemm(
    int M, int N, int K, int n0, int nsc,
    const __half* __restrict__ Ah, const __half* __restrict__ Al,
    const __half* __restrict__ B16,
    const float* __restrict__ bias, float* __restrict__ C,
    __half* __restrict__ Ch)
{
    extern __shared__ __half sm[];
    const int tid = threadIdx.x;
    const int bm = blockIdx.y;
    const int cb = n0 + blockIdx.x * BN;       // global column base
    const int wid = tid >> 5, lane = tid & 31;
    const int wm = (wid >> 1) * 32, wn = (wid & 1) * 64;

    const uint32_t smem_base = (uint32_t)__cvta_generic_to_shared(sm);

    float acc[2][8][4];
    #pragma unroll
    for (int mi = 0; mi < 2; mi++)
        #pragma unroll
        for (int nj = 0; nj < 8; nj++)
            #pragma unroll
            for (int r = 0; r < 4; r++) acc[mi][nj][r] = 0.f;

    const int NK = K / BKK;

    auto load_stage = [&](int s, int kt) {
        const uint32_t base = smem_base + s * (STAGE_H * 2);
        const int k0 = kt * BKK;
        #pragma unroll
        for (int i = 0; i < 4; i++) {
            int idx = tid + i * 256;
            int r = idx >> 3, c = (idx & 7) << 3;
            size_t aoff = (size_t)(bm * BM + r) * K + k0 + c;
            cp16(base + (OFF_AH + r * ALD + c) * 2, Ah + aoff);
            if (TERMS == 2)
                cp16(base + (OFF_AL + r * ALD + c) * 2, Al + aoff);
            int rb = idx >> 4, cbk = (idx & 15) << 3;
            size_t boff = (size_t)(k0 + rb) * N + cb + cbk;
            cp16(base + (OFF_B + rb * BLD + cbk) * 2, B16 + boff);
        }
        asm volatile("cp.async.commit_group;\n");
    };

    load_stage(0, 0);

    for (int kt = 0; kt < NK; kt++) {
        if (kt + 1 < NK) {
            load_stage((kt + 1) & 1, kt + 1);
            asm volatile("cp.async.wait_group 1;\n");
        } else {
            asm volatile("cp.async.wait_group 0;\n");
        }
        __syncthreads();

        const uint32_t base = smem_base + (kt & 1) * (STAGE_H * 2);

        #pragma unroll
        for (int ks = 0; ks < 4; ks++) {
            const int k = ks * 16;
            uint32_t ah[2][4], al[2][4];
            #pragma unroll
            for (int mi = 0; mi < 2; mi++) {
                int row = wm + mi * 16 + (lane & 15);
                int col = k + (lane >> 4) * 8;
                ldsm4(ah[mi][0], ah[mi][1], ah[mi][2], ah[mi][3],
                      base + (OFF_AH + row * ALD + col) * 2);
                if (TERMS == 2)
                    ldsm4(al[mi][0], al[mi][1], al[mi][2], al[mi][3],
                          base + (OFF_AL + row * ALD + col) * 2);
            }
            uint32_t bf[4][4];
            #pragma unroll
            for (int ng = 0; ng < 4; ng++) {
                int row = k + (lane & 15);
                int col = wn + ng * 16 + (lane >> 4) * 8;
                ldsm4t(bf[ng][0], bf[ng][1], bf[ng][2], bf[ng][3],
                       base + (OFF_B + row * BLD + col) * 2);
            }
            #pragma unroll
            for (int mi = 0; mi < 2; mi++) {
                #pragma unroll
                for (int nj = 0; nj < 8; nj++) {
                    const uint32_t* bp = &bf[nj >> 1][(nj & 1) * 2];
                    mma16816h(acc[mi][nj], ah[mi], bp);
                    if (TERMS == 2) mma16816h(acc[mi][nj], al[mi], bp);
                }
            }
        }
        __syncthreads();
    }

    const float cs = (OMODE == 1 && cb < nsc) ? 0.125f : 1.0f;
    #pragma unroll
    for (int mi = 0; mi < 2; mi++) {
        #pragma unroll
        for (int nj = 0; nj < 8; nj++) {
            int r0 = bm * BM + wm + mi * 16 + (lane >> 2);
            int c0 = cb + wn + nj * 8 + (lane & 3) * 2;
            float b0 = bias[c0], b1 = bias[c0 + 1];
            float v00 = (acc[mi][nj][0] + b0) * cs, v01 = (acc[mi][nj][1] + b1) * cs;
            float v10 = (acc[mi][nj][2] + b0) * cs, v11 = (acc[mi][nj][3] + b1) * cs;
            if (OMODE == 1) {
                *(uint32_t*)&Ch[(size_t)r0 * N + c0]       = pack2h(v00, v01);
                *(uint32_t*)&Ch[(size_t)(r0 + 8) * N + c0] = pack2h(v10, v11);
            } else {
                *(float2*)&C[(size_t)r0 * N + c0]       = make_float2(v00, v01);
                *(float2*)&C[(size_t)(r0 + 8) * N + c0] = make_float2(v10, v11);
            }
        }
    }
}

// ---------------------------------------------------------------------------
// Tensor-core flash attention: CTA = (64-query block, head, batch), 4 warps.
// All fp16 1-term: S = Qh Kh (Q pre-scaled), O += Ph Vh. ctx out fp16 (hi).
// ---------------------------------------------------------------------------
#define AP 72
#define ATT_SQ 0
#define ATT_STAGE0 (64 * AP)
#define ATT_STAGE_SZ (2 * 64 * AP)        // K + V
#define ATT_KH 0
#define ATT_VH (64 * AP)
#define ATT_SMEM ((64 * AP + 2 * 2 * 64 * AP) * 2)   // 46080 bytes

__global__ __launch_bounds__(128) void attn_tc(
    const __half* __restrict__ qkv,
    __half* __restrict__ ctx16)
{
    extern __shared__ __half smb[];
    const uint32_t sb = (uint32_t)__cvta_generic_to_shared(smb);
    const int qb = blockIdx.x, h = blockIdx.y, b = blockIdx.z;
    const int qs = qb * 64;
    const bool isg = (h < NGLOBAL);
    const int tid = threadIdx.x, lane = tid & 31, warp = tid >> 5;
    const int wq = warp * 16;
    const size_t rowbase = (size_t)(b * SEQ) * QKV_N;
    const float NEG_INF = __int_as_float(0xff800000u);

    // Q load (pre-scaled by 0.125 in GEMM1 epilogue)
    #pragma unroll
    for (int i = 0; i < 4; i++) {
        int idx = tid + i * 128;
        int r = idx >> 3, c8 = (idx & 7) * 8;
        size_t src = rowbase + (size_t)(qs + r) * QKV_N + h * HDIM + c8;
        cp16(sb + (ATT_SQ + r * AP + c8) * 2, qkv + src);
    }
    asm volatile("cp.async.commit_group;\n");

    const int kb0 = isg ? 0 : max(0, qb - 4);

    auto load_kv = [&](int kb, int s) {
        const uint32_t base = sb + (ATT_STAGE0 + s * ATT_STAGE_SZ) * 2;
        const int ks = kb * 64;
        #pragma unroll
        for (int i = 0; i < 4; i++) {
            int idx = tid + i * 128;
            int r = idx >> 3, c8 = (idx & 7) * 8;
            size_t src = rowbase + (size_t)(ks + r) * QKV_N + EMBED + h * HDIM + c8;
            cp16(base + (ATT_KH + r * AP + c8) * 2, qkv + src);
            cp16(base + (ATT_VH + r * AP + c8) * 2, qkv + src + EMBED);
        }
        asm volatile("cp.async.commit_group;\n");
    };

    load_kv(kb0, 0);

    float m0 = -1e30f, m1 = -1e30f, l0 = 0.f, l1 = 0.f;
    float O[8][4];
    #pragma unroll
    for (int nj = 0; nj < 8; nj++)
        #pragma unroll
        for (int r = 0; r < 4; r++) O[nj][r] = 0.f;

    uint32_t qf[4][4];
    bool qloaded = false;

    for (int kb = kb0; kb <= qb; kb++) {
        const int s = (kb - kb0) & 1;
        const int ks = kb * 64;
        __syncthreads();
        if (kb < qb) {
            load_kv(kb + 1, s ^ 1);
            asm volatile("cp.async.wait_group 1;\n");
        } else {
            asm volatile("cp.async.wait_group 0;\n");
        }
        __syncthreads();

        if (!qloaded) {
            qloaded = true;
            #pragma unroll
            for (int kt = 0; kt < 4; kt++) {
                uint32_t a = sb + (ATT_SQ + (wq + (lane & 15)) * AP
                                   + kt * 16 + 8 * (lane >> 4)) * 2;
                ldsm4(qf[kt][0], qf[kt][1], qf[kt][2], qf[kt][3], a);
            }
        }

        const uint32_t kbase = sb + (ATT_STAGE0 + s * ATT_STAGE_SZ) * 2;

        // ---- S = Qh Kh (1-term, pre-scaled) ----
        float sf[8][4];
        #pragma unroll
        for (int nj = 0; nj < 8; nj++)
            #pragma unroll
            for (int r = 0; r < 4; r++) sf[nj][r] = 0.f;

        #pragma unroll
        for (int kt = 0; kt < 4; kt++) {
            #pragma unroll
            for (int ng = 0; ng < 4; ng++) {
                uint32_t kh[4];
                uint32_t a = kbase + ((ng * 16 + (lane & 15)) * AP
                                      + kt * 16 + 8 * (lane >> 4)) * 2;
                ldsm4(kh[0], kh[1], kh[2], kh[3], a + ATT_KH * 2);
                uint32_t bh0[2] = {kh[0], kh[2]}, bh1[2] = {kh[1], kh[3]};
                mma16816h(sf[2 * ng],     qf[kt], bh0);
                mma16816h(sf[2 * ng + 1], qf[kt], bh1);
            }
        }

        // ---- mask ----
        const int i0 = qs + wq + (lane >> 2);
        const int i1 = i0 + 8;
        const int mode = (kb == qb) ? 1 : ((!isg && (qb - kb) == 4) ? 2 : 0);
        if (mode == 1) {
            #pragma unroll
            for (int nj = 0; nj < 8; nj++) {
                int j0 = ks + nj * 8 + (lane & 3) * 2, j1 = j0 + 1;
                if (j0 > i0) sf[nj][0] = NEG_INF;
                if (j1 > i0) sf[nj][1] = NEG_INF;
                if (j0 > i1) sf[nj][2] = NEG_INF;
                if (j1 > i1) sf[nj][3] = NEG_INF;
            }
        } else if (mode == 2) {
            #pragma unroll
            for (int nj = 0; nj < 8; nj++) {
                int j0 = ks + nj * 8 + (lane & 3) * 2, j1 = j0 + 1;
                if (i0 - j0 > WINDOW) sf[nj][0] = NEG_INF;
                if (i0 - j1 > WINDOW) sf[nj][1] = NEG_INF;
                if (i1 - j0 > WINDOW) sf[nj][2] = NEG_INF;
                if (i1 - j1 > WINDOW) sf[nj][3] = NEG_INF;
            }
        }

        // ---- online softmax ----
        float mx0 = -1e30f, mx1 = -1e30f;
        #pragma unroll
        for (int nj = 0; nj < 8; nj++) {
            mx0 = fmaxf(mx0, fmaxf(sf[nj][0], sf[nj][1]));
            mx1 = fmaxf(mx1, fmaxf(sf[nj][2], sf[nj][3]));
        }
        mx0 = fmaxf(mx0, __shfl_xor_sync(0xffffffffu, mx0, 1));
        mx0 = fmaxf(mx0, __shfl_xor_sync(0xffffffffu, mx0, 2));
        mx1 = fmaxf(mx1, __shfl_xor_sync(0xffffffffu, mx1, 1));
        mx1 = fmaxf(mx1, __shfl_xor_sync(0xffffffffu, mx1, 2));
        const float mn0 = fmaxf(m0, mx0), mn1 = fmaxf(m1, mx1);
        float s0 = 0.f, s1 = 0.f;
        #pragma unroll
        for (int nj = 0; nj < 8; nj++) {
            sf[nj][0] = __expf(sf[nj][0] - mn0);
            sf[nj][1] = __expf(sf[nj][1] - mn0);
            sf[nj][2] = __expf(sf[nj][2] - mn1);
            sf[nj][3] = __expf(sf[nj][3] - mn1);
            s0 += sf[nj][0] + sf[nj][1];
            s1 += sf[nj][2] + sf[nj][3];
        }
        s0 += __shfl_xor_sync(0xffffffffu, s0, 1);
        s0 += __shfl_xor_sync(0xffffffffu, s0, 2);
        s1 += __shfl_xor_sync(0xffffffffu, s1, 1);
        s1 += __shfl_xor_sync(0xffffffffu, s1, 2);
        const float a0 = __expf(m0 - mn0), a1 = __expf(m1 - mn1);
        l0 = l0 * a0 + s0; l1 = l1 * a1 + s1;
        m0 = mn0; m1 = mn1;
        #pragma unroll
        for (int nj = 0; nj < 8; nj++) {
            O[nj][0] *= a0; O[nj][1] *= a0;
            O[nj][2] *= a1; O[nj][3] *= a1;
        }

        // ---- O += Ph Vh (1-term) ----
        #pragma unroll
        for (int kt = 0; kt < 4; kt++) {
            uint32_t pah[4];
            pah[0] = pack2h(sf[2 * kt][0],     sf[2 * kt][1]);
            pah[1] = pack2h(sf[2 * kt][2],     sf[2 * kt][3]);
            pah[2] = pack2h(sf[2 * kt + 1][0], sf[2 * kt + 1][1]);
            pah[3] = pack2h(sf[2 * kt + 1][2], sf[2 * kt + 1][3]);
            #pragma unroll
            for (int ng = 0; ng < 4; ng++) {
                uint32_t vh[4];
                uint32_t a = kbase + ((kt * 16 + (lane & 15)) * AP
                                      + ng * 16 + 8 * (lane >> 4)) * 2;
                ldsm4t(vh[0], vh[1], vh[2], vh[3], a + ATT_VH * 2);
                mma16816h(O[2 * ng],     pah, &vh[0]);
                mma16816h(O[2 * ng + 1], pah, &vh[2]);
            }
        }
    }

    const float inv0 = 1.f / l0, inv1 = 1.f / l1;
    const int r0g = qs + wq + (lane >> 2);
    const size_t base0 = ((size_t)(b * SEQ + r0g)) * EMBED + h * HDIM;
    #pragma unroll
    for (int nj = 0; nj < 8; nj++) {
        const int c = nj * 8 + (lane & 3) * 2;
        *(uint32_t*)&ctx16[base0 + c] =
            pack2h(O[nj][0] * inv0, O[nj][1] * inv0);
        *(uint32_t*)&ctx16[base0 + (size_t)8 * EMBED + c] =
            pack2h(O[nj][2] * inv1, O[nj][3] * inv1);
    }
}

// ---------------------------------------------------------------------------
// Launch
// ---------------------------------------------------------------------------
extern "C" void kernel_launch(void* const* d_in, const int* in_sizes, int n_in,
                              void* d_out, int out_size)
{
    const float* x     = (const float*)d_in[0];
    const float* w_qkv = (const float*)d_in[1];
    const float* b_qkv = (const float*)d_in[2];
    const float* w_out = (const float*)d_in[3];
    const float* b_out = (const float*)d_in[4];
    float* out = (float*)d_out;

    __half *qkv16, *x16, *wq16, *wo16, *ctx16;
    cudaGetSymbolAddress((void**)&qkv16, g_qkv16);
    cudaGetSymbolAddress((void**)&x16,   g_x16);
    cudaGetSymbolAddress((void**)&wq16,  g_wq16);
    cudaGetSymbolAddress((void**)&wo16,  g_wo16);
    cudaGetSymbolAddress((void**)&ctx16, g_ctx16);

    cudaFuncSetAttribute((const void*)hsgemm<1, 1>,
                         cudaFuncAttributeMaxDynamicSharedMemorySize, GEMM_SMEM);
    cudaFuncSetAttribute((const void*)hsgemm<0, 1>,
                         cudaFuncAttributeMaxDynamicSharedMemorySize, GEMM_SMEM);
    cudaFuncSetAttribute(attn_tc, cudaFuncAttributeMaxDynamicSharedMemorySize, ATT_SMEM);

    // 0) fp16 conversions
    {
        int n4 = MROWS * EMBED / 4;
        cvth_kernel<<<(n4 + 255) / 256, 256>>>(x, x16, n4);
        n4 = EMBED * QKV_N / 4;
        cvth_kernel<<<(n4 + 255) / 256, 256>>>(w_qkv, wq16, n4);
        n4 = EMBED * EMBED / 4;
        cvth_kernel<<<(n4 + 255) / 256, 256>>>(w_out, wo16, n4);
    }

    // 1) QKV projection: single 1-term launch; Q columns scaled by 0.125
    {
        dim3 grid(QKV_N / BN, MROWS / BM);          // 24 x 64
        hsgemm<1, 1><<<grid, 256, GEMM_SMEM>>>(MROWS, QKV_N, EMBED, 0, EMBED,
                                               x16, nullptr, wq16, b_qkv,
                                               nullptr, qkv16);
    }
    // 2) Tensor-core attention (all 1-term) -> fp16 ctx
    {
        dim3 grid(SEQ / 64, HEADS, BATCH);
        attn_tc<<<grid, 128, ATT_SMEM>>>(qkv16, ctx16);
    }
    // 3) Output projection: 1-term -> fp32 out
    {
        dim3 grid(EMBED / BN, MROWS / BM);          // 8 x 64
        hsgemm<0, 1><<<grid, 256, GEMM_SMEM>>>(MROWS, EMBED, EMBED, 0, 0,
                                               ctx16, nullptr, wo16, b_out,
                                               out, nullptr);
    }
}